// round 1
// baseline (speedup 1.0000x reference)
#include <cuda_runtime.h>

#define M_ 2048
#define D_ 900
#define H_ 150
#define K_ 50
#define NEG_ (-1000000000.0f)

// Scratch (allocation-free: __device__ globals)
__device__ float g_P[M_ * H_];    // X @ W1a
__device__ float g_Q[M_ * H_];    // X @ W1b
__device__ float g_Hm[M_ * H_];   // X @ w1m
__device__ float g_ment[M_];

// ---------------------------------------------------------------------------
// Kernel A: C = X @ B  for three B's selected by blockIdx.z
//   X [2048,900], B [900,150], C [2048,150]
//   64x64 tile, BK=16, 256 threads, 4x4 micro-tile per thread
// ---------------------------------------------------------------------------
__global__ __launch_bounds__(256) void gemm_kernel(
    const float* __restrict__ X,
    const float* __restrict__ w1p,
    const float* __restrict__ w1m)
{
    const int z = blockIdx.z;
    const float* Bm = (z == 0) ? w1p : (z == 1) ? (w1p + D_ * H_) : w1m;
    float* C = (z == 0) ? g_P : (z == 1) ? g_Q : g_Hm;

    __shared__ float As[64][17];
    __shared__ float Bs[16][65];

    const int tx = threadIdx.x % 16;
    const int ty = threadIdx.x / 16;
    const int row0 = blockIdx.y * 64;
    const int col0 = blockIdx.x * 64;

    float acc[4][4] = {};

    for (int k0 = 0; k0 < D_; k0 += 16) {
        // A tile 64x16
        for (int idx = threadIdx.x; idx < 64 * 16; idx += 256) {
            int r = idx >> 4, kk = idx & 15;
            int k = k0 + kk;
            As[r][kk] = (k < D_) ? X[(row0 + r) * D_ + k] : 0.f;
        }
        // B tile 16x64
        for (int idx = threadIdx.x; idx < 16 * 64; idx += 256) {
            int kk = idx >> 6, c = idx & 63;
            int k = k0 + kk, col = col0 + c;
            Bs[kk][c] = (k < D_ && col < H_) ? Bm[k * H_ + col] : 0.f;
        }
        __syncthreads();
        #pragma unroll
        for (int kk = 0; kk < 16; ++kk) {
            float a[4], b[4];
            #pragma unroll
            for (int r = 0; r < 4; ++r) a[r] = As[ty * 4 + r][kk];
            #pragma unroll
            for (int c = 0; c < 4; ++c) b[c] = Bs[kk][tx * 4 + c];
            #pragma unroll
            for (int r = 0; r < 4; ++r)
                #pragma unroll
                for (int c = 0; c < 4; ++c)
                    acc[r][c] += a[r] * b[c];
        }
        __syncthreads();
    }

    #pragma unroll
    for (int r = 0; r < 4; ++r) {
        int row = row0 + ty * 4 + r;
        #pragma unroll
        for (int c = 0; c < 4; ++c) {
            int col = col0 + tx * 4 + c;
            if (col < H_) C[row * H_ + col] = acc[r][c];
        }
    }
}

// ---------------------------------------------------------------------------
// Kernel B: ment[i] = relu(Hm[i] + b1m) . w2m + b2m[0]
//   one warp per mention
// ---------------------------------------------------------------------------
__global__ __launch_bounds__(256) void ment_kernel(
    const float* __restrict__ b1m,
    const float* __restrict__ w2m,
    const float* __restrict__ b2m)
{
    const int warp = (blockIdx.x * blockDim.x + threadIdx.x) >> 5;
    const int lane = threadIdx.x & 31;
    if (warp >= M_) return;
    float s = 0.f;
    for (int h = lane; h < H_; h += 32) {
        float v = g_Hm[warp * H_ + h] + b1m[h];
        s += fmaxf(v, 0.f) * w2m[h];
    }
    #pragma unroll
    for (int o = 16; o > 0; o >>= 1) s += __shfl_xor_sync(0xffffffffu, s, o);
    if (lane == 0) g_ment[warp] = s + b2m[0];
}

// ---------------------------------------------------------------------------
// Kernel C: the dominant bilinear term + fused epilogue.
//   One CTA per mention i. For k in [0,50): j = i-K+k (clamped).
//   t3[k,h] = sum_d xi[d]*xj[d]*W1c[d,h]
//   score[i,k] = ment[i]+ment[j] + relu(t3 + P[i]+Q[j]+b1p) . w2p + b2p[0]
//   Thread layout: 8 warps; warp tk owns k in {tk, tk+8, ...} (7 values),
//   lane th owns h in {th, th+32, ..., th+128} (5 values) -> 35 accumulators.
// ---------------------------------------------------------------------------
__global__ __launch_bounds__(256) void score_kernel(
    const float* __restrict__ X,
    const float* __restrict__ w1p,
    const float* __restrict__ b1p,
    const float* __restrict__ w2p,
    const float* __restrict__ b2p,
    float* __restrict__ out)
{
    const int i = blockIdx.x;
    const float* __restrict__ W1c = w1p + 2 * D_ * H_;
    const int tid = threadIdx.x;
    const int th = tid & 31;   // lane -> h residue
    const int tk = tid >> 5;   // warp -> k residue (0..7)

    __shared__ float xi[D_];
    __shared__ float prod[56][33];   // k-padded to 56, +1 pad stride
    __shared__ float wt[32][160];    // W1c d-chunk, h padded to 160
    __shared__ float Pi[160];
    __shared__ float b1ps[160];
    __shared__ float w2ps[160];
    __shared__ float s_menti;

    for (int idx = tid; idx < D_; idx += 256) xi[idx] = X[i * D_ + idx];
    for (int idx = tid; idx < 160; idx += 256) {
        bool v = idx < H_;
        Pi[idx]   = v ? g_P[i * H_ + idx] : 0.f;
        b1ps[idx] = v ? b1p[idx] : 0.f;
        w2ps[idx] = v ? w2p[idx] : 0.f;
    }
    if (tid == 0) s_menti = g_ment[i];

    float acc[7][5];
    #pragma unroll
    for (int a = 0; a < 7; ++a)
        #pragma unroll
        for (int b = 0; b < 5; ++b) acc[a][b] = 0.f;

    __syncthreads();

    for (int t = 0; t < D_; t += 32) {
        // W1c tile: [32 d][160 h]
        for (int idx = tid; idx < 32 * 160; idx += 256) {
            int dd = idx / 160, h = idx % 160;
            int d = t + dd;
            wt[dd][h] = (h < H_ && d < D_) ? W1c[d * H_ + h] : 0.f;
        }
        // prod tile: xi[d] * X[j,d] for each k
        for (int idx = tid; idx < 56 * 32; idx += 256) {
            int k = idx >> 5, dd = idx & 31;
            int d = t + dd;
            float v = 0.f;
            if (k < K_ && d < D_) {
                int j = i - K_ + k;
                if (j < 0) j = 0;
                v = xi[d] * X[j * D_ + d];
            }
            prod[k][dd] = v;
        }
        __syncthreads();

        #pragma unroll 4
        for (int dd = 0; dd < 32; ++dd) {
            float wv[5], xp[7];
            #pragma unroll
            for (int hh = 0; hh < 5; ++hh) wv[hh] = wt[dd][th + 32 * hh];
            #pragma unroll
            for (int kk = 0; kk < 7; ++kk) xp[kk] = prod[tk + 8 * kk][dd];
            #pragma unroll
            for (int kk = 0; kk < 7; ++kk)
                #pragma unroll
                for (int hh = 0; hh < 5; ++hh)
                    acc[kk][hh] += xp[kk] * wv[hh];
        }
        __syncthreads();
    }

    const float menti = s_menti;
    const float b2p0 = b2p[0];

    #pragma unroll
    for (int kk = 0; kk < 7; ++kk) {
        int k = tk + 8 * kk;
        float partial = 0.f;
        if (k < K_) {
            int j = i - K_ + k;
            int jc = (j < 0) ? 0 : j;
            #pragma unroll
            for (int hh = 0; hh < 5; ++hh) {
                int h = th + 32 * hh;
                if (h < H_) {
                    float a = acc[kk][hh] + Pi[h] + g_Q[jc * H_ + h] + b1ps[h];
                    partial += fmaxf(a, 0.f) * w2ps[h];
                }
            }
        }
        // full-warp reduction over h lanes (k is uniform across the warp)
        #pragma unroll
        for (int o = 16; o > 0; o >>= 1)
            partial += __shfl_xor_sync(0xffffffffu, partial, o);
        if (th == 0 && k < K_) {
            int j = i - K_ + k;
            float score = (j >= 0)
                ? (menti + g_ment[j] + partial + b2p0)
                : NEG_;
            out[i * (K_ + 1) + k] = score;
        }
    }
    if (tid == 0) out[i * (K_ + 1) + K_] = 0.f;  // dummy column
}

// ---------------------------------------------------------------------------
extern "C" void kernel_launch(void* const* d_in, const int* in_sizes, int n_in,
                              void* d_out, int out_size)
{
    const float* X   = (const float*)d_in[0];
    const float* w1m = (const float*)d_in[1];
    const float* b1m = (const float*)d_in[2];
    const float* w2m = (const float*)d_in[3];
    const float* b2m = (const float*)d_in[4];
    const float* w1p = (const float*)d_in[5];
    const float* b1p = (const float*)d_in[6];
    const float* w2p = (const float*)d_in[7];
    const float* b2p = (const float*)d_in[8];
    float* out = (float*)d_out;

    dim3 ggrid(3, M_ / 64, 3);           // 192 cols (guarded to 150), 2048 rows, 3 mats
    gemm_kernel<<<ggrid, 256>>>(X, w1p, w1m);
    ment_kernel<<<M_ / 8, 256>>>(b1m, w2m, b2m);   // 2048 warps
    score_kernel<<<M_, 256>>>(X, w1p, b1p, w2p, b2p, out);
}

// round 3
// speedup vs baseline: 3.7687x; 3.7687x over previous
#include <cuda_runtime.h>
#include <cuda_bf16.h>
#include <cstdint>

#define M_ 2048
#define D_ 900
#define H_ 150
#define K_ 50
#define NEG_ (-1000000000.0f)
#define NCH 29         // d chunks of 32 (928 padded)
#define DP 928

// ---- scratch (allocation-free) ----
__device__ float g_gp[9][M_ * H_];
__device__ float g_P[M_ * H_];
__device__ float g_Q[M_ * H_];
__device__ float g_Hm[M_ * H_];
__device__ float g_ment[M_];
__device__ __align__(16) __nv_bfloat16 g_Wt[160 * DP];   // W1c transposed [h][d], bf16, zero-padded

// ============================ helpers ============================
__device__ __forceinline__ uint32_t smem_u32(const void* p) {
    uint32_t a;
    asm("{ .reg .u64 t; cvta.to.shared.u64 t, %1; cvt.u32.u64 %0, t; }" : "=r"(a) : "l"(p));
    return a;
}
#define CVT_BF2(res, lo, hi) asm("cvt.rn.bf16x2.f32 %0, %1, %2;" : "=r"(res) : "f"(hi), "f"(lo))
#define STS128(a, r0, r1, r2, r3) asm volatile("st.shared.v4.b32 [%0], {%1,%2,%3,%4};" :: "r"(a), "r"(r0), "r"(r1), "r"(r2), "r"(r3) : "memory")
#define LDSM_X4(r0, r1, r2, r3, addr) \
    asm volatile("ldmatrix.sync.aligned.m8n8.x4.shared.b16 {%0,%1,%2,%3}, [%4];" \
        : "=r"(r0), "=r"(r1), "=r"(r2), "=r"(r3) : "r"(addr))
#define LDSM_X2(r0, r1, addr) \
    asm volatile("ldmatrix.sync.aligned.m8n8.x2.shared.b16 {%0,%1}, [%2];" \
        : "=r"(r0), "=r"(r1) : "r"(addr))
#define MMA16816(c, a0, a1, a2, a3, b0, b1) \
    asm volatile("mma.sync.aligned.m16n8k16.row.col.f32.bf16.bf16.f32 " \
        "{%0,%1,%2,%3},{%4,%5,%6,%7},{%8,%9},{%0,%1,%2,%3};" \
        : "+f"((c)[0]), "+f"((c)[1]), "+f"((c)[2]), "+f"((c)[3]) \
        : "r"(a0), "r"(a1), "r"(a2), "r"(a3), "r"(b0), "r"(b1))

// ============================ Kernel A: K-split fp32 GEMMs ============================
__global__ __launch_bounds__(256) void gemm_part_kernel(
    const float* __restrict__ X, const float* __restrict__ w1p, const float* __restrict__ w1m)
{
    const int z = blockIdx.z;
    const int mat = z % 3, slice = z / 3;
    const float* Bm = (mat == 0) ? w1p : (mat == 1) ? (w1p + D_ * H_) : w1m;
    float* C = g_gp[z];
    const int kbeg = slice * 300, kend = kbeg + 300;

    __shared__ float As[64][17];
    __shared__ float Bs[16][65];
    const int tx = threadIdx.x % 16, ty = threadIdx.x / 16;
    const int row0 = blockIdx.y * 64, col0 = blockIdx.x * 64;
    float acc[4][4] = {};

    for (int k0 = kbeg; k0 < kend; k0 += 16) {
        for (int idx = threadIdx.x; idx < 64 * 16; idx += 256) {
            int r = idx >> 4, kk = idx & 15, k = k0 + kk;
            As[r][kk] = (k < kend) ? X[(row0 + r) * D_ + k] : 0.f;
        }
        for (int idx = threadIdx.x; idx < 16 * 64; idx += 256) {
            int kk = idx >> 6, c = idx & 63, k = k0 + kk, col = col0 + c;
            Bs[kk][c] = (k < kend && col < H_) ? Bm[k * H_ + col] : 0.f;
        }
        __syncthreads();
        #pragma unroll
        for (int kk = 0; kk < 16; ++kk) {
            float a[4], b[4];
            #pragma unroll
            for (int r = 0; r < 4; ++r) a[r] = As[ty * 4 + r][kk];
            #pragma unroll
            for (int c = 0; c < 4; ++c) b[c] = Bs[kk][tx * 4 + c];
            #pragma unroll
            for (int r = 0; r < 4; ++r)
                #pragma unroll
                for (int c = 0; c < 4; ++c) acc[r][c] += a[r] * b[c];
        }
        __syncthreads();
    }
    #pragma unroll
    for (int r = 0; r < 4; ++r) {
        int row = row0 + ty * 4 + r;
        #pragma unroll
        for (int c = 0; c < 4; ++c) {
            int col = col0 + tx * 4 + c;
            if (col < H_) C[row * H_ + col] = acc[r][c];
        }
    }
}

__global__ __launch_bounds__(256) void combine_kernel() {
    int idx = blockIdx.x * 256 + threadIdx.x;
    if (idx < M_ * H_) {
        g_P[idx]  = g_gp[0][idx] + g_gp[3][idx] + g_gp[6][idx];
        g_Q[idx]  = g_gp[1][idx] + g_gp[4][idx] + g_gp[7][idx];
        g_Hm[idx] = g_gp[2][idx] + g_gp[5][idx] + g_gp[8][idx];
    }
}

// ============================ Kernel B: ment ============================
__global__ __launch_bounds__(256) void ment_kernel(
    const float* __restrict__ b1m, const float* __restrict__ w2m, const float* __restrict__ b2m)
{
    const int warp = (blockIdx.x * blockDim.x + threadIdx.x) >> 5;
    const int lane = threadIdx.x & 31;
    if (warp >= M_) return;
    float s = 0.f;
    for (int h = lane; h < H_; h += 32) {
        float v = g_Hm[warp * H_ + h] + b1m[h];
        s += fmaxf(v, 0.f) * w2m[h];
    }
    #pragma unroll
    for (int o = 16; o > 0; o >>= 1) s += __shfl_xor_sync(0xffffffffu, s, o);
    if (lane == 0) g_ment[warp] = s + b2m[0];
}

// ============================ W1c transpose prep (bf16 [h][d]) ============================
__global__ __launch_bounds__(256) void wt_prep_kernel(const float* __restrict__ w1p) {
    int idx = blockIdx.x * 256 + threadIdx.x;
    if (idx >= 160 * DP) return;
    int h = idx / DP, d = idx % DP;
    float v = (h < H_ && d < D_) ? w1p[2 * D_ * H_ + d * H_ + h] : 0.f;
    g_Wt[h * DP + d] = __float2bfloat16(v);
}

// ============================ Kernel C: mma.sync score ============================
// CTA: 2 mentions (i0, i0+1). A[128 rows][32 d] bf16 products, row = m*64+k.
// B = W1c^T chunk [160 h][32 d] bf16. acc[row][h] += sum_d A*B.
// 8 warps: warp w owns rows 16w..16w+15, all 160 cols (20 n8-tiles).
__global__ __launch_bounds__(256, 2) void score_mma_kernel(
    const float* __restrict__ X,
    const float* __restrict__ b1p,
    const float* __restrict__ w2p,
    const float* __restrict__ b2p,
    float* __restrict__ out)
{
    __shared__ __align__(16) unsigned char Asm[128 * 80];  // 80B row stride (64B data + 16 pad)
    __shared__ __align__(16) unsigned char Bsm[160 * 80];
    __shared__ float Ps[2][160];
    __shared__ float w2ps[160];

    const int tid = threadIdx.x;
    const int wid = tid >> 5;
    const int lane = tid & 31;
    const int i0 = blockIdx.x * 2;

    for (int idx = tid; idx < 320; idx += 256) {
        int m = idx / 160, h = idx % 160;
        Ps[m][h] = (h < H_) ? (g_P[(i0 + m) * H_ + h] + b1p[h]) : 0.f;
    }
    for (int idx = tid; idx < 160; idx += 256) w2ps[idx] = (idx < H_) ? w2p[idx] : 0.f;

    const uint32_t Abase = smem_u32(Asm);
    const uint32_t Bbase = smem_u32(Bsm);
    // ldmatrix lane addresses
    const uint32_t a_addr = Abase + (uint32_t)(wid * 16 + (lane & 15)) * 80 + ((lane >> 4) & 1) * 16;
    const uint32_t b_addr0 = Bbase + (uint32_t)(lane & 7) * 80 + ((lane >> 3) & 1) * 16;

    float acc[20][4];
    #pragma unroll
    for (int nt = 0; nt < 20; ++nt)
        #pragma unroll
        for (int q = 0; q < 4; ++q) acc[nt][q] = 0.f;

    __syncthreads();  // Ps/w2ps visible (and before first A/B writes ordering)

    for (int c = 0; c < NCH; ++c) {
        // B chunk: copy g_Wt[:, 32c:32c+32] -> Bsm (rows padded to 80B)
        for (int idx = tid; idx < 640; idx += 256) {
            int h = idx >> 2, grp = idx & 3;
            uint4 v = *(const uint4*)((const char*)g_Wt + h * (DP * 2) + c * 64 + grp * 16);
            *(uint4*)(Bsm + h * 80 + grp * 16) = v;
        }
        // A chunk: bf16 products xi*xj. 400 tasks: (row 0..99) x (grp 0..3, 8 d each)
        const int d0c = c * 32;
        #pragma unroll
        for (int it = 0; it < 2; ++it) {
            int t = tid + it * 256;
            if (t < 400) {
                int rr = t >> 2, grp = t & 3;
                int m = (rr >= 50) ? 1 : 0;
                int k = rr - 50 * m;
                int gi = i0 + m;
                int gj = gi + k - K_; if (gj < 0) gj = 0;
                int d = d0c + grp * 8;
                float4 z = make_float4(0.f, 0.f, 0.f, 0.f);
                float4 xi0 = z, xi1 = z, xj0 = z, xj1 = z;
                if (d < D_) {
                    xi0 = __ldg((const float4*)(X + gi * D_ + d));
                    xj0 = __ldg((const float4*)(X + gj * D_ + d));
                }
                if (d + 4 < D_) {
                    xi1 = __ldg((const float4*)(X + gi * D_ + d + 4));
                    xj1 = __ldg((const float4*)(X + gj * D_ + d + 4));
                }
                uint32_t r0, r1, r2, r3;
                CVT_BF2(r0, xi0.x * xj0.x, xi0.y * xj0.y);
                CVT_BF2(r1, xi0.z * xj0.z, xi0.w * xj0.w);
                CVT_BF2(r2, xi1.x * xj1.x, xi1.y * xj1.y);
                CVT_BF2(r3, xi1.z * xj1.z, xi1.w * xj1.w);
                int Arow = m * 64 + k;
                STS128(Abase + (uint32_t)(Arow * 80 + grp * 16), r0, r1, r2, r3);
            }
        }
        __syncthreads();

        // MMA: 2 k16 steps, 20 n-tiles
        #pragma unroll
        for (int k16 = 0; k16 < 2; ++k16) {
            uint32_t a0, a1, a2, a3;
            LDSM_X4(a0, a1, a2, a3, a_addr + k16 * 32);
            #pragma unroll
            for (int nt = 0; nt < 20; ++nt) {
                uint32_t b0, b1;
                LDSM_X2(b0, b1, b_addr0 + (uint32_t)(nt * 8 * 80) + k16 * 32);
                MMA16816(acc[nt], a0, a1, a2, a3, b0, b1);
            }
        }
        __syncthreads();
    }

    // ---- fused epilogue ----
    const float b2p0 = __ldg(b2p);
    const int g = lane >> 2, t = lane & 3;
    const int r0 = wid * 16 + g, r1 = r0 + 8;
    const int m0 = r0 >> 6, k0 = r0 & 63;
    const int m1 = r1 >> 6, k1 = r1 & 63;
    const int j0 = i0 + m0 + k0 - K_;
    const int j1 = i0 + m1 + k1 - K_;
    const bool v0 = (k0 < K_), v1 = (k1 < K_);
    const float* q0 = g_Q + ((j0 < 0) ? 0 : j0) * H_;
    const float* q1 = g_Q + ((j1 < 0) ? 0 : j1) * H_;

    float p0 = 0.f, p1 = 0.f;
    #pragma unroll
    for (int nt = 0; nt < 20; ++nt) {
        int hb = nt * 8 + t * 2;
        if (hb < H_) {   // hb is even; hb<=148 -> hb+1<=149 valid
            float wa = w2ps[hb], wb = w2ps[hb + 1];
            if (v0) {
                float a = acc[nt][0] + Ps[m0][hb]     + __ldg(q0 + hb);
                float b = acc[nt][1] + Ps[m0][hb + 1] + __ldg(q0 + hb + 1);
                p0 += fmaxf(a, 0.f) * wa + fmaxf(b, 0.f) * wb;
            }
            if (v1) {
                float a = acc[nt][2] + Ps[m1][hb]     + __ldg(q1 + hb);
                float b = acc[nt][3] + Ps[m1][hb + 1] + __ldg(q1 + hb + 1);
                p1 += fmaxf(a, 0.f) * wa + fmaxf(b, 0.f) * wb;
            }
        }
    }
    p0 += __shfl_xor_sync(0xffffffffu, p0, 1);
    p0 += __shfl_xor_sync(0xffffffffu, p0, 2);
    p1 += __shfl_xor_sync(0xffffffffu, p1, 1);
    p1 += __shfl_xor_sync(0xffffffffu, p1, 2);

    if (t == 0) {
        if (v0) out[(i0 + m0) * (K_ + 1) + k0] =
            (j0 >= 0) ? (g_ment[i0 + m0] + g_ment[j0] + b2p0 + p0) : NEG_;
        if (v1) out[(i0 + m1) * (K_ + 1) + k1] =
            (j1 >= 0) ? (g_ment[i0 + m1] + g_ment[j1] + b2p0 + p1) : NEG_;
    }
    if (tid < 2) out[(i0 + tid) * (K_ + 1) + K_] = 0.f;
}

// ============================ launcher ============================
extern "C" void kernel_launch(void* const* d_in, const int* in_sizes, int n_in,
                              void* d_out, int out_size)
{
    const float* X   = (const float*)d_in[0];
    const float* w1m = (const float*)d_in[1];
    const float* b1m = (const float*)d_in[2];
    const float* w2m = (const float*)d_in[3];
    const float* b2m = (const float*)d_in[4];
    const float* w1p = (const float*)d_in[5];
    const float* b1p = (const float*)d_in[6];
    const float* w2p = (const float*)d_in[7];
    const float* b2p = (const float*)d_in[8];
    float* out = (float*)d_out;

    dim3 ggrid(3, M_ / 64, 9);
    gemm_part_kernel<<<ggrid, 256>>>(X, w1p, w1m);
    combine_kernel<<<(M_ * H_ + 255) / 256, 256>>>();
    ment_kernel<<<M_ / 8, 256>>>(b1m, w2m, b2m);
    wt_prep_kernel<<<(160 * DP + 255) / 256, 256>>>(w1p);
    score_mma_kernel<<<M_ / 2, 256>>>(X, b1p, w2p, b2p, out);
}

// round 4
// speedup vs baseline: 6.5480x; 1.7375x over previous
#include <cuda_runtime.h>
#include <cuda_bf16.h>
#include <cstdint>

#define M_ 2048
#define D_ 900
#define H_ 150
#define K_ 50
#define NEG_ (-1000000000.0f)
#define NCH 29
#define DP 928
#define XB_ROWB 1856           // bytes per g_Xb row
#define GPC 5                  // mentions per score CTA (250 rows -> 256)
#define SGRID ((M_ + GPC - 1) / GPC)   // 410

// ---- scratch ----
__device__ float g_P[M_ * H_];
__device__ float g_Q[M_ * H_];
__device__ float g_Hm[M_ * H_];
__device__ float g_ment[M_];
__device__ __align__(16) __nv_bfloat16 g_Xb[M_ * DP];        // X bf16, d padded to 928
__device__ __align__(16) __nv_bfloat16 g_Wabm[480 * DP];     // [w1a|w1b|w1m]^T bf16 [n][d]
__device__ __align__(16) __nv_bfloat16 g_Wt[160 * DP];       // W1c^T bf16 [h][d]

// ============================ helpers ============================
__device__ __forceinline__ uint32_t smem_u32(const void* p) {
    uint32_t a;
    asm("{ .reg .u64 t; cvta.to.shared.u64 t, %1; cvt.u32.u64 %0, t; }" : "=r"(a) : "l"(p));
    return a;
}
__device__ __forceinline__ uint32_t bf2mul(uint32_t a, uint32_t b) {
    __nv_bfloat162 x, y, z;
    *(uint32_t*)&x = a; *(uint32_t*)&y = b;
    z = __hmul2(x, y);
    return *(uint32_t*)&z;
}
#define STS128(a, r0, r1, r2, r3) asm volatile("st.shared.v4.b32 [%0], {%1,%2,%3,%4};" :: "r"(a), "r"(r0), "r"(r1), "r"(r2), "r"(r3) : "memory")
#define LDSM_X4(r0, r1, r2, r3, addr) \
    asm volatile("ldmatrix.sync.aligned.m8n8.x4.shared.b16 {%0,%1,%2,%3}, [%4];" \
        : "=r"(r0), "=r"(r1), "=r"(r2), "=r"(r3) : "r"(addr))
#define LDSM_X2(r0, r1, addr) \
    asm volatile("ldmatrix.sync.aligned.m8n8.x2.shared.b16 {%0,%1}, [%2];" \
        : "=r"(r0), "=r"(r1) : "r"(addr))
#define MMA16816(c, a0, a1, a2, a3, b0, b1) \
    asm volatile("mma.sync.aligned.m16n8k16.row.col.f32.bf16.bf16.f32 " \
        "{%0,%1,%2,%3},{%4,%5,%6,%7},{%8,%9},{%0,%1,%2,%3};" \
        : "+f"((c)[0]), "+f"((c)[1]), "+f"((c)[2]), "+f"((c)[3]) \
        : "r"(a0), "r"(a1), "r"(a2), "r"(a3), "r"(b0), "r"(b1))

// ============================ prep: all bf16 images ============================
#define N0 (M_ * DP)
#define N1 (480 * DP)
#define N2 (160 * DP)
__global__ __launch_bounds__(256) void prep_kernel(
    const float* __restrict__ X, const float* __restrict__ w1p, const float* __restrict__ w1m)
{
    int idx = blockIdx.x * 256 + threadIdx.x;
    if (idx < N0) {
        int row = idx / DP, d = idx % DP;
        g_Xb[idx] = __float2bfloat16(d < D_ ? X[row * D_ + d] : 0.f);
    } else if (idx < N0 + N1) {
        int r = idx - N0;
        int n = r / DP, d = r % DP;
        int mat = n / 160, h = n % 160;
        float v = 0.f;
        if (h < H_ && d < D_)
            v = (mat == 0) ? w1p[d * H_ + h]
              : (mat == 1) ? w1p[D_ * H_ + d * H_ + h]
                           : w1m[d * H_ + h];
        g_Wabm[r] = __float2bfloat16(v);
    } else if (idx < N0 + N1 + N2) {
        int r = idx - N0 - N1;
        int h = r / DP, d = r % DP;
        float v = (h < H_ && d < D_) ? w1p[2 * D_ * H_ + d * H_ + h] : 0.f;
        g_Wt[r] = __float2bfloat16(v);
    }
}

// ============================ bf16 MMA GEMM for P/Q/Hm ============================
// C[2048][3*160] = Xb @ Wabm^T.  CTA tile: M=64, N=160 (one mat). grid (32, 3).
__global__ __launch_bounds__(256) void gemm_mma_kernel()
{
    __shared__ __align__(16) unsigned char Asm[64 * 80];
    __shared__ __align__(16) unsigned char Bsm[160 * 80];

    const int tid = threadIdx.x;
    const int wid = tid >> 5;
    const int lane = tid & 31;
    const int row0 = blockIdx.x * 64;
    const int mat = blockIdx.y;
    const char* Bsrc = (const char*)(g_Wabm + mat * 160 * DP);

    const uint32_t Ab = smem_u32(Asm);
    const uint32_t Bb = smem_u32(Bsm);
    const uint32_t a_off = Ab + (uint32_t)(((wid & 3) * 16 + (lane & 15)) * 80 + ((lane >> 4) & 1) * 16);
    const uint32_t b_off = Bb + (uint32_t)(((wid >> 2) * 80 + (lane & 7)) * 80 + ((lane >> 3) & 1) * 16);

    float acc[10][4];
    #pragma unroll
    for (int nt = 0; nt < 10; ++nt)
        #pragma unroll
        for (int q = 0; q < 4; ++q) acc[nt][q] = 0.f;

    for (int c = 0; c < NCH; ++c) {
        {   // A: 64 rows x 4 grps
            int r = tid >> 2, grp = tid & 3;
            uint4 v = __ldg((const uint4*)((const char*)g_Xb + (row0 + r) * XB_ROWB + c * 64 + grp * 16));
            *(uint4*)(Asm + r * 80 + grp * 16) = v;
        }
        for (int idx = tid; idx < 640; idx += 256) {   // B: 160 rows x 4 grps
            int h = idx >> 2, grp = idx & 3;
            uint4 v = __ldg((const uint4*)(Bsrc + h * XB_ROWB + c * 64 + grp * 16));
            *(uint4*)(Bsm + h * 80 + grp * 16) = v;
        }
        __syncthreads();
        #pragma unroll
        for (int k16 = 0; k16 < 2; ++k16) {
            uint32_t a0, a1, a2, a3;
            LDSM_X4(a0, a1, a2, a3, a_off + k16 * 32);
            #pragma unroll
            for (int nt = 0; nt < 10; ++nt) {
                uint32_t b0, b1;
                LDSM_X2(b0, b1, b_off + nt * 640 + k16 * 32);
                MMA16816(acc[nt], a0, a1, a2, a3, b0, b1);
            }
        }
        __syncthreads();
    }

    float* dst = (mat == 0) ? g_P : (mat == 1) ? g_Q : g_Hm;
    const int g = lane >> 2, t = lane & 3;
    #pragma unroll
    for (int nt = 0; nt < 10; ++nt) {
        int h = (wid >> 2) * 80 + nt * 8 + t * 2;
        if (h < H_) {
            int ra = row0 + (wid & 3) * 16 + g;
            dst[ra * H_ + h]           = acc[nt][0];
            dst[ra * H_ + h + 1]       = acc[nt][1];
            dst[(ra + 8) * H_ + h]     = acc[nt][2];
            dst[(ra + 8) * H_ + h + 1] = acc[nt][3];
        }
    }
}

// ============================ ment ============================
__global__ __launch_bounds__(256) void ment_kernel(
    const float* __restrict__ b1m, const float* __restrict__ w2m, const float* __restrict__ b2m)
{
    const int warp = (blockIdx.x * blockDim.x + threadIdx.x) >> 5;
    const int lane = threadIdx.x & 31;
    if (warp >= M_) return;
    float s = 0.f;
    for (int h = lane; h < H_; h += 32) {
        float v = g_Hm[warp * H_ + h] + b1m[h];
        s += fmaxf(v, 0.f) * w2m[h];
    }
    #pragma unroll
    for (int o = 16; o > 0; o >>= 1) s += __shfl_xor_sync(0xffffffffu, s, o);
    if (lane == 0) g_ment[warp] = s + b2m[0];
}

// ============================ score: 5 mentions/CTA, pipelined ============================
// dyn smem layout (bytes):
#define SA0 0
#define SA1 20480
#define SB0 40960
#define SB1 53760
#define SPS 66560      // 5*160 f32
#define SW2 69760      // 160 f32
#define SSZ 70400

__global__ __launch_bounds__(512, 1) void score_mma_kernel(
    const float* __restrict__ b1p,
    const float* __restrict__ w2p,
    const float* __restrict__ b2p,
    float* __restrict__ out)
{
    extern __shared__ __align__(16) unsigned char sm[];
    const int tid = threadIdx.x;
    const int wid = tid >> 5;
    const int lane = tid & 31;
    const int i0 = blockIdx.x * GPC;

    float* Ps = (float*)(sm + SPS);
    float* w2ps = (float*)(sm + SW2);
    const uint32_t Sb = smem_u32(sm);

    // stage Ps (P + b1p, clamped mention rows) and w2p
    for (int idx = tid; idx < GPC * 160; idx += 512) {
        int m = idx / 160, h = idx % 160;
        int i = i0 + m; if (i > M_ - 1) i = M_ - 1;
        Ps[idx] = (h < H_) ? (g_P[i * H_ + h] + b1p[h]) : 0.f;
    }
    for (int idx = tid; idx < 160; idx += 512) w2ps[idx] = (idx < H_) ? w2p[idx] : 0.f;
    // zero A pad rows 250..255 (both buffers) — disjoint from build writes
    if (tid < 48) {
        int buf = tid & 1, rem = tid >> 1;
        int row = 250 + (rem >> 2), grp = rem & 3;
        uint4 z = make_uint4(0, 0, 0, 0);
        *(uint4*)(sm + (buf ? SA1 : SA0) + row * 80 + grp * 16) = z;
    }

    // ---- build chunk 0 directly ----
    {
        const int c = 0;
        for (int it = 0; it < 2; ++it) {
            int t = tid + it * 512;
            if (t < 1000) {
                int rr = t >> 2, grp = t & 3;
                int m = rr / 50, k = rr - m * 50;
                int i = i0 + m; if (i > M_ - 1) i = M_ - 1;
                int j = i0 + m + k - K_; if (j < 0) j = 0; if (j > M_ - 1) j = M_ - 1;
                uint4 va = __ldg((const uint4*)((const char*)g_Xb + i * XB_ROWB + c * 64 + grp * 16));
                uint4 vb = __ldg((const uint4*)((const char*)g_Xb + j * XB_ROWB + c * 64 + grp * 16));
                STS128(Sb + SA0 + rr * 80 + grp * 16,
                       bf2mul(va.x, vb.x), bf2mul(va.y, vb.y),
                       bf2mul(va.z, vb.z), bf2mul(va.w, vb.w));
            }
        }
        for (int idx = tid; idx < 640; idx += 512) {
            int h = idx >> 2, grp = idx & 3;
            uint4 v = __ldg((const uint4*)((const char*)g_Wt + h * XB_ROWB + c * 64 + grp * 16));
            *(uint4*)(sm + SB0 + h * 80 + grp * 16) = v;
        }
    }
    __syncthreads();

    const uint32_t a_off = (uint32_t)((wid * 16 + (lane & 15)) * 80 + ((lane >> 4) & 1) * 16);
    const uint32_t b_off = (uint32_t)((lane & 7) * 80 + ((lane >> 3) & 1) * 16);

    float acc[20][4];
    #pragma unroll
    for (int nt = 0; nt < 20; ++nt)
        #pragma unroll
        for (int q = 0; q < 4; ++q) acc[nt][q] = 0.f;

    for (int c = 0; c < NCH; ++c) {
        const bool has = (c + 1 < NCH);
        // ---- stage next chunk in registers (loads fly under the MMAs) ----
        uint4 pa0, pa1, sb0, sb1;
        int rr0 = tid >> 2, rr1 = (tid + 512) >> 2;
        if (has) {
            const int cn = c + 1;
            {   // A task 0: t = tid
                int grp = tid & 3;
                int m = rr0 / 50, k = rr0 - m * 50;
                int i = i0 + m; if (i > M_ - 1) i = M_ - 1;
                int j = i0 + m + k - K_; if (j < 0) j = 0; if (j > M_ - 1) j = M_ - 1;
                uint4 va = __ldg((const uint4*)((const char*)g_Xb + i * XB_ROWB + cn * 64 + grp * 16));
                uint4 vb = __ldg((const uint4*)((const char*)g_Xb + j * XB_ROWB + cn * 64 + grp * 16));
                pa0.x = bf2mul(va.x, vb.x); pa0.y = bf2mul(va.y, vb.y);
                pa0.z = bf2mul(va.z, vb.z); pa0.w = bf2mul(va.w, vb.w);
            }
            if (tid + 512 < 1000) {   // A task 1
                int grp = tid & 3;
                int m = rr1 / 50, k = rr1 - m * 50;
                int i = i0 + m; if (i > M_ - 1) i = M_ - 1;
                int j = i0 + m + k - K_; if (j < 0) j = 0; if (j > M_ - 1) j = M_ - 1;
                uint4 va = __ldg((const uint4*)((const char*)g_Xb + i * XB_ROWB + cn * 64 + grp * 16));
                uint4 vb = __ldg((const uint4*)((const char*)g_Xb + j * XB_ROWB + cn * 64 + grp * 16));
                pa1.x = bf2mul(va.x, vb.x); pa1.y = bf2mul(va.y, vb.y);
                pa1.z = bf2mul(va.z, vb.z); pa1.w = bf2mul(va.w, vb.w);
            }
            {   // B tasks
                int h = tid >> 2, grp = tid & 3;
                if (tid < 640)
                    sb0 = __ldg((const uint4*)((const char*)g_Wt + h * XB_ROWB + cn * 64 + grp * 16));
                if (tid < 128)
                    sb1 = __ldg((const uint4*)((const char*)g_Wt + (h + 128) * XB_ROWB + cn * 64 + grp * 16));
            }
        }

        // ---- MMA on current buffer ----
        const uint32_t ab = Sb + ((c & 1) ? SA1 : SA0) + a_off;
        const uint32_t bb = Sb + ((c & 1) ? SB1 : SB0) + b_off;
        #pragma unroll
        for (int k16 = 0; k16 < 2; ++k16) {
            uint32_t a0, a1, a2, a3;
            LDSM_X4(a0, a1, a2, a3, ab + k16 * 32);
            #pragma unroll
            for (int nt = 0; nt < 20; ++nt) {
                uint32_t b0, b1;
                LDSM_X2(b0, b1, bb + nt * 640 + k16 * 32);
                MMA16816(acc[nt], a0, a1, a2, a3, b0, b1);
            }
        }

        // ---- store staged chunk into the other buffer ----
        if (has) {
            const uint32_t an = Sb + ((c & 1) ? SA0 : SA1);
            const uint32_t bn = Sb + ((c & 1) ? SB0 : SB1);
            int grp = tid & 3;
            STS128(an + rr0 * 80 + grp * 16, pa0.x, pa0.y, pa0.z, pa0.w);
            if (tid + 512 < 1000)
                STS128(an + rr1 * 80 + grp * 16, pa1.x, pa1.y, pa1.z, pa1.w);
            if (tid < 640)
                *(uint4*)((unsigned char*)sm + (bn - Sb) + (tid >> 2) * 80 + grp * 16) = sb0;
            if (tid < 128)
                *(uint4*)((unsigned char*)sm + (bn - Sb) + ((tid >> 2) + 128) * 80 + grp * 16) = sb1;
        }
        __syncthreads();
    }

    // ---- fused epilogue ----
    const float b2p0 = __ldg(b2p);
    const int g = lane >> 2, t = lane & 3;
    #pragma unroll
    for (int half = 0; half < 2; ++half) {
        const int r = wid * 16 + g + half * 8;
        if (r < 250) {
            const int m = r / 50, k = r - m * 50;
            const int i = i0 + m;
            const int j = i0 + m + k - K_;
            const int jc = (j < 0) ? 0 : j;
            const float* qrow = g_Q + jc * H_;
            const float* prow = Ps + m * 160;
            float p = 0.f;
            if (i < M_ && j >= 0) {
                #pragma unroll
                for (int nt = 0; nt < 20; ++nt) {
                    int hb = nt * 8 + t * 2;
                    if (hb < H_) {
                        float a = acc[nt][half * 2]     + prow[hb]     + __ldg(qrow + hb);
                        float b = acc[nt][half * 2 + 1] + prow[hb + 1] + __ldg(qrow + hb + 1);
                        p += fmaxf(a, 0.f) * w2ps[hb] + fmaxf(b, 0.f) * w2ps[hb + 1];
                    }
                }
            }
            p += __shfl_xor_sync(0xffffffffu, p, 1);
            p += __shfl_xor_sync(0xffffffffu, p, 2);
            if (t == 0 && i < M_) {
                out[i * (K_ + 1) + k] = (j >= 0)
                    ? (g_ment[i] + g_ment[j] + b2p0 + p) : NEG_;
            }
        }
    }
    if (tid < GPC) {
        int i = i0 + tid;
        if (i < M_) out[i * (K_ + 1) + K_] = 0.f;
    }
}

// ============================ launcher ============================
extern "C" void kernel_launch(void* const* d_in, const int* in_sizes, int n_in,
                              void* d_out, int out_size)
{
    const float* X   = (const float*)d_in[0];
    const float* w1m = (const float*)d_in[1];
    const float* b1m = (const float*)d_in[2];
    const float* w2m = (const float*)d_in[3];
    const float* b2m = (const float*)d_in[4];
    const float* w1p = (const float*)d_in[5];
    const float* b1p = (const float*)d_in[6];
    const float* w2p = (const float*)d_in[7];
    const float* b2p = (const float*)d_in[8];
    float* out = (float*)d_out;

    cudaFuncSetAttribute(score_mma_kernel,
                         cudaFuncAttributeMaxDynamicSharedMemorySize, SSZ);

    const int TOT = N0 + N1 + N2;
    prep_kernel<<<(TOT + 255) / 256, 256>>>(X, w1p, w1m);
    gemm_mma_kernel<<<dim3(32, 3), 256>>>();
    ment_kernel<<<M_ / 8, 256>>>(b1m, w2m, b2m);
    score_mma_kernel<<<SGRID, 512, SSZ>>>(b1p, w2p, b2p, out);
}

// round 5
// speedup vs baseline: 6.8833x; 1.0512x over previous
#include <cuda_runtime.h>
#include <cuda_bf16.h>
#include <cstdint>

#define M_ 2048
#define D_ 900
#define H_ 150
#define K_ 50
#define NEG_ (-1000000000.0f)
#define NCH 29
#define DP 928
#define XB_ROWB 1856
#define GPC 5
#define SGRID ((M_ + GPC - 1) / GPC)   // 410

// ---- scratch ----
__device__ float g_P[M_ * H_];
__device__ float g_Q[M_ * H_];
__device__ float g_Hm[M_ * H_];
__device__ float g_ment[M_];
__device__ __align__(16) __nv_bfloat16 g_Xb[M_ * DP];
__device__ __align__(16) __nv_bfloat16 g_Wabm[480 * DP];
__device__ __align__(16) __nv_bfloat16 g_Wt[160 * DP];

// ============================ helpers ============================
__device__ __forceinline__ uint32_t smem_u32(const void* p) {
    uint32_t a;
    asm("{ .reg .u64 t; cvta.to.shared.u64 t, %1; cvt.u32.u64 %0, t; }" : "=r"(a) : "l"(p));
    return a;
}
__device__ __forceinline__ uint32_t bf2mul(uint32_t a, uint32_t b) {
    __nv_bfloat162 x, y, z;
    *(uint32_t*)&x = a; *(uint32_t*)&y = b;
    z = __hmul2(x, y);
    return *(uint32_t*)&z;
}
#define STS128(a, r0, r1, r2, r3) asm volatile("st.shared.v4.b32 [%0], {%1,%2,%3,%4};" :: "r"(a), "r"(r0), "r"(r1), "r"(r2), "r"(r3) : "memory")
#define LDSM_X4(r0, r1, r2, r3, addr) \
    asm volatile("ldmatrix.sync.aligned.m8n8.x4.shared.b16 {%0,%1,%2,%3}, [%4];" \
        : "=r"(r0), "=r"(r1), "=r"(r2), "=r"(r3) : "r"(addr))
#define LDSM_X2(r0, r1, addr) \
    asm volatile("ldmatrix.sync.aligned.m8n8.x2.shared.b16 {%0,%1}, [%2];" \
        : "=r"(r0), "=r"(r1) : "r"(addr))
#define MMA16816(c, a0, a1, a2, a3, b0, b1) \
    asm volatile("mma.sync.aligned.m16n8k16.row.col.f32.bf16.bf16.f32 " \
        "{%0,%1,%2,%3},{%4,%5,%6,%7},{%8,%9},{%0,%1,%2,%3};" \
        : "+f"((c)[0]), "+f"((c)[1]), "+f"((c)[2]), "+f"((c)[3]) \
        : "r"(a0), "r"(a1), "r"(a2), "r"(a3), "r"(b0), "r"(b1))

// ============================ prep ============================
#define N0 (M_ * DP)
#define N1 (480 * DP)
#define N2 (160 * DP)
__global__ __launch_bounds__(256) void prep_kernel(
    const float* __restrict__ X, const float* __restrict__ w1p, const float* __restrict__ w1m)
{
    int idx = blockIdx.x * 256 + threadIdx.x;
    if (idx < N0) {
        int row = idx / DP, d = idx % DP;
        g_Xb[idx] = __float2bfloat16(d < D_ ? X[row * D_ + d] : 0.f);
    } else if (idx < N0 + N1) {
        int r = idx - N0;
        int n = r / DP, d = r % DP;
        int mat = n / 160, h = n % 160;
        float v = 0.f;
        if (h < H_ && d < D_)
            v = (mat == 0) ? w1p[d * H_ + h]
              : (mat == 1) ? w1p[D_ * H_ + d * H_ + h]
                           : w1m[d * H_ + h];
        g_Wabm[r] = __float2bfloat16(v);
    } else if (idx < N0 + N1 + N2) {
        int r = idx - N0 - N1;
        int h = r / DP, d = r % DP;
        float v = (h < H_ && d < D_) ? w1p[2 * D_ * H_ + d * H_ + h] : 0.f;
        g_Wt[r] = __float2bfloat16(v);
    }
}

// ============================ bf16 MMA GEMM for P/Q/Hm ============================
__global__ __launch_bounds__(256) void gemm_mma_kernel()
{
    __shared__ __align__(16) unsigned char Asm[64 * 80];
    __shared__ __align__(16) unsigned char Bsm[160 * 80];

    const int tid = threadIdx.x;
    const int wid = tid >> 5;
    const int lane = tid & 31;
    const int row0 = blockIdx.x * 64;
    const int mat = blockIdx.y;
    const char* Bsrc = (const char*)(g_Wabm + mat * 160 * DP);

    const uint32_t Ab = smem_u32(Asm);
    const uint32_t Bb = smem_u32(Bsm);
    const uint32_t a_off = Ab + (uint32_t)(((wid & 3) * 16 + (lane & 15)) * 80 + ((lane >> 4) & 1) * 16);
    const uint32_t b_off = Bb + (uint32_t)(((wid >> 2) * 80 + (lane & 7)) * 80 + ((lane >> 3) & 1) * 16);

    float acc[10][4];
    #pragma unroll
    for (int nt = 0; nt < 10; ++nt)
        #pragma unroll
        for (int q = 0; q < 4; ++q) acc[nt][q] = 0.f;

    for (int c = 0; c < NCH; ++c) {
        {
            int r = tid >> 2, grp = tid & 3;
            uint4 v = __ldg((const uint4*)((const char*)g_Xb + (row0 + r) * XB_ROWB + c * 64 + grp * 16));
            *(uint4*)(Asm + r * 80 + grp * 16) = v;
        }
        for (int idx = tid; idx < 640; idx += 256) {
            int h = idx >> 2, grp = idx & 3;
            uint4 v = __ldg((const uint4*)(Bsrc + h * XB_ROWB + c * 64 + grp * 16));
            *(uint4*)(Bsm + h * 80 + grp * 16) = v;
        }
        __syncthreads();
        #pragma unroll
        for (int k16 = 0; k16 < 2; ++k16) {
            uint32_t a0, a1, a2, a3;
            LDSM_X4(a0, a1, a2, a3, a_off + k16 * 32);
            #pragma unroll
            for (int nt = 0; nt < 10; ++nt) {
                uint32_t b0, b1;
                LDSM_X2(b0, b1, b_off + nt * 640 + k16 * 32);
                MMA16816(acc[nt], a0, a1, a2, a3, b0, b1);
            }
        }
        __syncthreads();
    }

    float* dst = (mat == 0) ? g_P : (mat == 1) ? g_Q : g_Hm;
    const int g = lane >> 2, t = lane & 3;
    #pragma unroll
    for (int nt = 0; nt < 10; ++nt) {
        int h = (wid >> 2) * 80 + nt * 8 + t * 2;
        if (h < H_) {
            int ra = row0 + (wid & 3) * 16 + g;
            dst[ra * H_ + h]           = acc[nt][0];
            dst[ra * H_ + h + 1]       = acc[nt][1];
            dst[(ra + 8) * H_ + h]     = acc[nt][2];
            dst[(ra + 8) * H_ + h + 1] = acc[nt][3];
        }
    }
}

// ============================ ment ============================
__global__ __launch_bounds__(256) void ment_kernel(
    const float* __restrict__ b1m, const float* __restrict__ w2m, const float* __restrict__ b2m)
{
    const int warp = (blockIdx.x * blockDim.x + threadIdx.x) >> 5;
    const int lane = threadIdx.x & 31;
    if (warp >= M_) return;
    float s = 0.f;
    for (int h = lane; h < H_; h += 32) {
        float v = g_Hm[warp * H_ + h] + b1m[h];
        s += fmaxf(v, 0.f) * w2m[h];
    }
    #pragma unroll
    for (int o = 16; o > 0; o >>= 1) s += __shfl_xor_sync(0xffffffffu, s, o);
    if (lane == 0) g_ment[warp] = s + b2m[0];
}

// ============================ score: 32m x 80n warp tiles, x4 B loads ============================
#define SA0 0
#define SA1 20480
#define SB0 40960
#define SB1 53760
#define SPS 66560      // 5*160 f32
#define SW2 69760      // 160 f32
#define SPART 70400    // 2*256 f32
#define SSZ 72448

__global__ __launch_bounds__(512, 1) void score_mma_kernel(
    const float* __restrict__ b1p,
    const float* __restrict__ w2p,
    const float* __restrict__ b2p,
    float* __restrict__ out)
{
    extern __shared__ __align__(16) unsigned char sm[];
    const int tid = threadIdx.x;
    const int wid = tid >> 5;
    const int lane = tid & 31;
    const int i0 = blockIdx.x * GPC;

    float* Ps = (float*)(sm + SPS);
    float* w2ps = (float*)(sm + SW2);
    float* part = (float*)(sm + SPART);
    const uint32_t Sb = smem_u32(sm);

    for (int idx = tid; idx < GPC * 160; idx += 512) {
        int m = idx / 160, h = idx % 160;
        int i = i0 + m; if (i > M_ - 1) i = M_ - 1;
        Ps[idx] = (h < H_) ? (g_P[i * H_ + h] + b1p[h]) : 0.f;
    }
    for (int idx = tid; idx < 160; idx += 512) w2ps[idx] = (idx < H_) ? w2p[idx] : 0.f;
    // zero A pad rows 250..255 both buffers
    if (tid < 48) {
        int buf = tid & 1, rem = tid >> 1;
        int row = 250 + (rem >> 2), grp = rem & 3;
        uint4 z = make_uint4(0, 0, 0, 0);
        *(uint4*)(sm + (buf ? SA1 : SA0) + row * 80 + grp * 16) = z;
    }

    // ---- build chunk 0 ----
    {
        const int c = 0;
        for (int it = 0; it < 2; ++it) {
            int t = tid + it * 512;
            if (t < 1000) {
                int rr = t >> 2, grp = t & 3;
                int m = rr / 50, k = rr - m * 50;
                int i = i0 + m; if (i > M_ - 1) i = M_ - 1;
                int j = i0 + m + k - K_; if (j < 0) j = 0; if (j > M_ - 1) j = M_ - 1;
                uint4 va = __ldg((const uint4*)((const char*)g_Xb + i * XB_ROWB + c * 64 + grp * 16));
                uint4 vb = __ldg((const uint4*)((const char*)g_Xb + j * XB_ROWB + c * 64 + grp * 16));
                STS128(Sb + SA0 + rr * 80 + grp * 16,
                       bf2mul(va.x, vb.x), bf2mul(va.y, vb.y),
                       bf2mul(va.z, vb.z), bf2mul(va.w, vb.w));
            }
        }
        for (int idx = tid; idx < 640; idx += 512) {
            int h = idx >> 2, grp = idx & 3;
            uint4 v = __ldg((const uint4*)((const char*)g_Wt + h * XB_ROWB + c * 64 + grp * 16));
            *(uint4*)(sm + SB0 + h * 80 + grp * 16) = v;
        }
    }
    __syncthreads();

    const int mgrp = wid & 7;     // 32-row group
    const int ngrp = wid >> 3;    // 80-col group
    // A: m-tile t at rows mgrp*32 + t*16
    const uint32_t a_off = (uint32_t)((mgrp * 32 + (lane & 15)) * 80 + ((lane >> 4) & 1) * 16);
    // B paired x4: lanes 0-15 -> rows p*16.. (first n8), lanes 16-31 -> +8 rows
    const uint32_t b_off = (uint32_t)((ngrp * 80 + ((lane >> 4) & 1) * 8 + (lane & 7)) * 80
                                      + ((lane >> 3) & 1) * 16);

    float acc[2][10][4];
    #pragma unroll
    for (int t = 0; t < 2; ++t)
        #pragma unroll
        for (int nt = 0; nt < 10; ++nt)
            #pragma unroll
            for (int q = 0; q < 4; ++q) acc[t][nt][q] = 0.f;

    for (int c = 0; c < NCH; ++c) {
        const bool has = (c + 1 < NCH);
        uint4 pa0, pa1, sb0, sb1;
        int rr0 = tid >> 2, rr1 = (tid + 512) >> 2;
        if (has) {
            const int cn = c + 1;
            {
                int grp = tid & 3;
                int m = rr0 / 50, k = rr0 - m * 50;
                int i = i0 + m; if (i > M_ - 1) i = M_ - 1;
                int j = i0 + m + k - K_; if (j < 0) j = 0; if (j > M_ - 1) j = M_ - 1;
                uint4 va = __ldg((const uint4*)((const char*)g_Xb + i * XB_ROWB + cn * 64 + grp * 16));
                uint4 vb = __ldg((const uint4*)((const char*)g_Xb + j * XB_ROWB + cn * 64 + grp * 16));
                pa0.x = bf2mul(va.x, vb.x); pa0.y = bf2mul(va.y, vb.y);
                pa0.z = bf2mul(va.z, vb.z); pa0.w = bf2mul(va.w, vb.w);
            }
            if (tid + 512 < 1000) {
                int grp = tid & 3;
                int m = rr1 / 50, k = rr1 - m * 50;
                int i = i0 + m; if (i > M_ - 1) i = M_ - 1;
                int j = i0 + m + k - K_; if (j < 0) j = 0; if (j > M_ - 1) j = M_ - 1;
                uint4 va = __ldg((const uint4*)((const char*)g_Xb + i * XB_ROWB + cn * 64 + grp * 16));
                uint4 vb = __ldg((const uint4*)((const char*)g_Xb + j * XB_ROWB + cn * 64 + grp * 16));
                pa1.x = bf2mul(va.x, vb.x); pa1.y = bf2mul(va.y, vb.y);
                pa1.z = bf2mul(va.z, vb.z); pa1.w = bf2mul(va.w, vb.w);
            }
            {
                int h = tid >> 2, grp = tid & 3;
                if (tid < 640)
                    sb0 = __ldg((const uint4*)((const char*)g_Wt + h * XB_ROWB + cn * 64 + grp * 16));
                if (tid < 128)
                    sb1 = __ldg((const uint4*)((const char*)g_Wt + (h + 128) * XB_ROWB + cn * 64 + grp * 16));
            }
        }

        // ---- MMA on current buffer ----
        const uint32_t ab = Sb + ((c & 1) ? SA1 : SA0) + a_off;
        const uint32_t bb = Sb + ((c & 1) ? SB1 : SB0) + b_off;
        #pragma unroll
        for (int k16 = 0; k16 < 2; ++k16) {
            uint32_t a0[4], a1[4];
            LDSM_X4(a0[0], a0[1], a0[2], a0[3], ab + k16 * 32);
            LDSM_X4(a1[0], a1[1], a1[2], a1[3], ab + 16 * 80 + k16 * 32);
            #pragma unroll
            for (int p = 0; p < 5; ++p) {
                uint32_t b0, b1, b2, b3;
                LDSM_X4(b0, b1, b2, b3, bb + p * 1280 + k16 * 32);
                MMA16816(acc[0][2 * p],     a0[0], a0[1], a0[2], a0[3], b0, b1);
                MMA16816(acc[0][2 * p + 1], a0[0], a0[1], a0[2], a0[3], b2, b3);
                MMA16816(acc[1][2 * p],     a1[0], a1[1], a1[2], a1[3], b0, b1);
                MMA16816(acc[1][2 * p + 1], a1[0], a1[1], a1[2], a1[3], b2, b3);
            }
        }

        if (has) {
            const uint32_t an = Sb + ((c & 1) ? SA0 : SA1);
            const uint32_t bn = Sb + ((c & 1) ? SB0 : SB1);
            int grp = tid & 3;
            STS128(an + rr0 * 80 + grp * 16, pa0.x, pa0.y, pa0.z, pa0.w);
            if (tid + 512 < 1000)
                STS128(an + rr1 * 80 + grp * 16, pa1.x, pa1.y, pa1.z, pa1.w);
            if (tid < 640)
                *(uint4*)((unsigned char*)sm + (bn - Sb) + (tid >> 2) * 80 + grp * 16) = sb0;
            if (tid < 128)
                *(uint4*)((unsigned char*)sm + (bn - Sb) + ((tid >> 2) + 128) * 80 + grp * 16) = sb1;
        }
        __syncthreads();
    }

    // ---- epilogue: per-warp 80-col partials, cross-warp combine ----
    const int g = lane >> 2, t4 = lane & 3;
    #pragma unroll
    for (int t = 0; t < 2; ++t) {
        #pragma unroll
        for (int half = 0; half < 2; ++half) {
            const int r = mgrp * 32 + t * 16 + half * 8 + g;
            float p = 0.f;
            if (r < 250) {
                const int m = r / 50, k = r - m * 50;
                const int i = i0 + m;
                const int j = i0 + m + k - K_;
                if (i < M_ && j >= 0) {
                    const float* qrow = g_Q + j * H_;
                    const float* prow = Ps + m * 160;
                    #pragma unroll
                    for (int nt = 0; nt < 10; ++nt) {
                        int hb = ngrp * 80 + nt * 8 + t4 * 2;
                        if (hb < H_) {
                            float a = acc[t][nt][half * 2]     + prow[hb]     + __ldg(qrow + hb);
                            float b = acc[t][nt][half * 2 + 1] + prow[hb + 1] + __ldg(qrow + hb + 1);
                            p += fmaxf(a, 0.f) * w2ps[hb] + fmaxf(b, 0.f) * w2ps[hb + 1];
                        }
                    }
                }
            }
            p += __shfl_xor_sync(0xffffffffu, p, 1);
            p += __shfl_xor_sync(0xffffffffu, p, 2);
            if (t4 == 0 && r < 250) part[ngrp * 256 + r] = p;
        }
    }
    __syncthreads();

    const float b2p0 = __ldg(b2p);
    if (tid < 250) {
        const int r = tid;
        const int m = r / 50, k = r - m * 50;
        const int i = i0 + m;
        const int j = i0 + m + k - K_;
        if (i < M_) {
            out[i * (K_ + 1) + k] = (j >= 0)
                ? (g_ment[i] + g_ment[j] + b2p0 + part[r] + part[256 + r]) : NEG_;
        }
    }
    if (tid >= 480 && tid < 480 + GPC) {
        int i = i0 + (tid - 480);
        if (i < M_) out[i * (K_ + 1) + K_] = 0.f;
    }
}

// ============================ launcher ============================
extern "C" void kernel_launch(void* const* d_in, const int* in_sizes, int n_in,
                              void* d_out, int out_size)
{
    const float* X   = (const float*)d_in[0];
    const float* w1m = (const float*)d_in[1];
    const float* b1m = (const float*)d_in[2];
    const float* w2m = (const float*)d_in[3];
    const float* b2m = (const float*)d_in[4];
    const float* w1p = (const float*)d_in[5];
    const float* b1p = (const float*)d_in[6];
    const float* w2p = (const float*)d_in[7];
    const float* b2p = (const float*)d_in[8];
    float* out = (float*)d_out;

    cudaFuncSetAttribute(score_mma_kernel,
                         cudaFuncAttributeMaxDynamicSharedMemorySize, SSZ);

    const int TOT = N0 + N1 + N2;
    prep_kernel<<<(TOT + 255) / 256, 256>>>(X, w1p, w1m);
    gemm_mma_kernel<<<dim3(32, 3), 256>>>();
    ment_kernel<<<M_ / 8, 256>>>(b1m, w2m, b2m);
    score_mma_kernel<<<SGRID, 512, SSZ>>>(b1p, w2p, b2p, out);
}

// round 8
// speedup vs baseline: 7.3394x; 1.0663x over previous
#include <cuda_runtime.h>
#include <cuda_bf16.h>
#include <cstdint>

#define M_ 2048
#define D_ 900
#define H_ 150
#define K_ 50
#define NEG_ (-1000000000.0f)
#define NCH 29
#define DP 928
#define XB_ROWB 1856
#define GPC 5
#define SGRID ((M_ + GPC - 1) / GPC)   // 410

// score kernel smem layout (bytes)
#define XWST 80            // X-window row stride
#define XWSZ (56 * 80)     // 4480 per buffer
#define BSZ  (160 * 80)    // 12800 per buffer
#define SXW 0              // 3 * 4480 = 13440
#define SB  13440          // 3 * 12800 = 38400
#define SPS 51840          // 5*160 f32
#define SW2 55040          // 160 f32
#define SPART 55680        // 2*256 f32
#define SSZ 57728
#define XWSZ_OR_B(t) ((t) < 224 ? XWSZ : BSZ)

// ---- scratch ----
__device__ float g_P[M_ * H_];
__device__ float g_Q[M_ * H_];
__device__ float g_Hm[M_ * H_];
__device__ float g_ment[M_];
__device__ __align__(16) __nv_bfloat16 g_Xb[M_ * DP];
__device__ __align__(16) __nv_bfloat16 g_Wabm[480 * DP];
__device__ __align__(16) __nv_bfloat16 g_Wt[160 * DP];

// ============================ helpers ============================
__device__ __forceinline__ uint32_t smem_u32(const void* p) {
    uint32_t a;
    asm("{ .reg .u64 t; cvta.to.shared.u64 t, %1; cvt.u32.u64 %0, t; }" : "=r"(a) : "l"(p));
    return a;
}
__device__ __forceinline__ uint32_t bf2mul(uint32_t a, uint32_t b) {
    __nv_bfloat162 x, y, z;
    *(uint32_t*)&x = a; *(uint32_t*)&y = b;
    z = __hmul2(x, y);
    return *(uint32_t*)&z;
}
__device__ __forceinline__ void cp16(uint32_t dst, const void* src) {
    asm volatile("cp.async.cg.shared.global [%0], [%1], 16;" :: "r"(dst), "l"(src) : "memory");
}
#define CP_COMMIT() asm volatile("cp.async.commit_group;" ::: "memory")
#define CP_WAIT1()  asm volatile("cp.async.wait_group 1;" ::: "memory")
#define CP_WAIT0()  asm volatile("cp.async.wait_group 0;" ::: "memory")
#define LDSM_X4(r0, r1, r2, r3, addr) \
    asm volatile("ldmatrix.sync.aligned.m8n8.x4.shared.b16 {%0,%1,%2,%3}, [%4];" \
        : "=r"(r0), "=r"(r1), "=r"(r2), "=r"(r3) : "r"(addr))
#define LDSM_X2(r0, r1, addr) \
    asm volatile("ldmatrix.sync.aligned.m8n8.x2.shared.b16 {%0,%1}, [%2];" \
        : "=r"(r0), "=r"(r1) : "r"(addr))
#define MMA16816(c, a0, a1, a2, a3, b0, b1) \
    asm volatile("mma.sync.aligned.m16n8k16.row.col.f32.bf16.bf16.f32 " \
        "{%0,%1,%2,%3},{%4,%5,%6,%7},{%8,%9},{%0,%1,%2,%3};" \
        : "+f"((c)[0]), "+f"((c)[1]), "+f"((c)[2]), "+f"((c)[3]) \
        : "r"(a0), "r"(a1), "r"(a2), "r"(a3), "r"(b0), "r"(b1))

// ============================ prep ============================
#define N0 (M_ * DP)
#define N1 (480 * DP)
#define N2 (160 * DP)
__global__ __launch_bounds__(256) void prep_kernel(
    const float* __restrict__ X, const float* __restrict__ w1p, const float* __restrict__ w1m)
{
    int idx = blockIdx.x * 256 + threadIdx.x;
    if (idx < N0) {
        int row = idx / DP, d = idx % DP;
        g_Xb[idx] = __float2bfloat16(d < D_ ? X[row * D_ + d] : 0.f);
    } else if (idx < N0 + N1) {
        int r = idx - N0;
        int n = r / DP, d = r % DP;
        int mat = n / 160, h = n % 160;
        float v = 0.f;
        if (h < H_ && d < D_)
            v = (mat == 0) ? w1p[d * H_ + h]
              : (mat == 1) ? w1p[D_ * H_ + d * H_ + h]
                           : w1m[d * H_ + h];
        g_Wabm[r] = __float2bfloat16(v);
    } else if (idx < N0 + N1 + N2) {
        int r = idx - N0 - N1;
        int h = r / DP, d = r % DP;
        float v = (h < H_ && d < D_) ? w1p[2 * D_ * H_ + d * H_ + h] : 0.f;
        g_Wt[r] = __float2bfloat16(v);
    }
}

// ============================ bf16 MMA GEMM for P/Q/Hm ============================
__global__ __launch_bounds__(256) void gemm_mma_kernel()
{
    __shared__ __align__(16) unsigned char Asm[64 * 80];
    __shared__ __align__(16) unsigned char Bsm[160 * 80];

    const int tid = threadIdx.x;
    const int wid = tid >> 5;
    const int lane = tid & 31;
    const int row0 = blockIdx.x * 64;
    const int mat = blockIdx.y;
    const char* Bsrc = (const char*)(g_Wabm + mat * 160 * DP);

    const uint32_t Ab = smem_u32(Asm);
    const uint32_t Bb = smem_u32(Bsm);
    const uint32_t a_off = Ab + (uint32_t)(((wid & 3) * 16 + (lane & 15)) * 80 + ((lane >> 4) & 1) * 16);
    const uint32_t b_off = Bb + (uint32_t)(((wid >> 2) * 80 + (lane & 7)) * 80 + ((lane >> 3) & 1) * 16);

    float acc[10][4];
    #pragma unroll
    for (int nt = 0; nt < 10; ++nt)
        #pragma unroll
        for (int q = 0; q < 4; ++q) acc[nt][q] = 0.f;

    for (int c = 0; c < NCH; ++c) {
        {
            int r = tid >> 2, grp = tid & 3;
            uint4 v = __ldg((const uint4*)((const char*)g_Xb + (row0 + r) * XB_ROWB + c * 64 + grp * 16));
            *(uint4*)(Asm + r * 80 + grp * 16) = v;
        }
        for (int idx = tid; idx < 640; idx += 256) {
            int h = idx >> 2, grp = idx & 3;
            uint4 v = __ldg((const uint4*)(Bsrc + h * XB_ROWB + c * 64 + grp * 16));
            *(uint4*)(Bsm + h * 80 + grp * 16) = v;
        }
        __syncthreads();
        #pragma unroll
        for (int k16 = 0; k16 < 2; ++k16) {
            uint32_t a0, a1, a2, a3;
            LDSM_X4(a0, a1, a2, a3, a_off + k16 * 32);
            #pragma unroll
            for (int nt = 0; nt < 10; ++nt) {
                uint32_t b0, b1;
                LDSM_X2(b0, b1, b_off + nt * 640 + k16 * 32);
                MMA16816(acc[nt], a0, a1, a2, a3, b0, b1);
            }
        }
        __syncthreads();
    }

    float* dst = (mat == 0) ? g_P : (mat == 1) ? g_Q : g_Hm;
    const int g = lane >> 2, t = lane & 3;
    #pragma unroll
    for (int nt = 0; nt < 10; ++nt) {
        int h = (wid >> 2) * 80 + nt * 8 + t * 2;
        if (h < H_) {
            int ra = row0 + (wid & 3) * 16 + g;
            dst[ra * H_ + h]           = acc[nt][0];
            dst[ra * H_ + h + 1]       = acc[nt][1];
            dst[(ra + 8) * H_ + h]     = acc[nt][2];
            dst[(ra + 8) * H_ + h + 1] = acc[nt][3];
        }
    }
}

// ============================ ment ============================
__global__ __launch_bounds__(256) void ment_kernel(
    const float* __restrict__ b1m, const float* __restrict__ w2m, const float* __restrict__ b2m)
{
    const int warp = (blockIdx.x * blockDim.x + threadIdx.x) >> 5;
    const int lane = threadIdx.x & 31;
    if (warp >= M_) return;
    float s = 0.f;
    for (int h = lane; h < H_; h += 32) {
        float v = g_Hm[warp * H_ + h] + b1m[h];
        s += fmaxf(v, 0.f) * w2m[h];
    }
    #pragma unroll
    for (int o = 16; o > 0; o >>= 1) s += __shfl_xor_sync(0xffffffffu, s, o);
    if (lane == 0) g_ment[warp] = s + b2m[0];
}

// ============================ score: X-window + in-register A fragments ============================
__global__ __launch_bounds__(512, 1) void score_mma_kernel(
    const float* __restrict__ b1p,
    const float* __restrict__ w2p,
    const float* __restrict__ b2p,
    float* __restrict__ out)
{
    extern __shared__ __align__(16) unsigned char sm[];
    const int tid = threadIdx.x;
    const int wid = tid >> 5;
    const int lane = tid & 31;
    const int i0 = blockIdx.x * GPC;

    float* Ps = (float*)(sm + SPS);
    float* w2ps = (float*)(sm + SW2);
    float* part = (float*)(sm + SPART);
    const uint32_t Sb = smem_u32(sm);

    // cp.async task mapping (fixed per thread):
    //  tid 0..223:  X-window row rr=tid>>2, 16B group grp=tid&3
    //  tid 224..511: B rows 0..71 ; second slot tid<352: B rows 72..159
    uint32_t dst0; const char* src0base;
    if (tid < 224) {
        int rr = tid >> 2, grp = tid & 3;
        int gr = i0 - K_ + rr;
        if (gr < 0) gr = 0; if (gr > M_ - 1) gr = M_ - 1;
        dst0 = Sb + SXW + (uint32_t)(rr * XWST + grp * 16);
        src0base = (const char*)g_Xb + gr * XB_ROWB + grp * 16;
    } else {
        int idx = tid - 224;
        int h = idx >> 2, grp = idx & 3;
        dst0 = Sb + SB + (uint32_t)(h * 80 + grp * 16);
        src0base = (const char*)g_Wt + h * XB_ROWB + grp * 16;
    }
    uint32_t dst1 = 0; const char* src1base = nullptr;
    if (tid < 352) {
        int idx = tid + 288;
        int h = idx >> 2, grp = idx & 3;
        dst1 = Sb + SB + (uint32_t)(h * 80 + grp * 16);
        src1base = (const char*)g_Wt + h * XB_ROWB + grp * 16;
    }

    // prologue: issue chunks 0 and 1
    cp16(dst0, src0base);
    if (tid < 352) cp16(dst1, src1base);
    CP_COMMIT();
    cp16(dst0 + (uint32_t)XWSZ_OR_B(tid), src0base + 64);
    if (tid < 352) cp16(dst1 + BSZ, src1base + 64);
    CP_COMMIT();

    // stage Ps / w2p
    for (int idx = tid; idx < GPC * 160; idx += 512) {
        int m = idx / 160, h = idx % 160;
        int i = i0 + m; if (i > M_ - 1) i = M_ - 1;
        Ps[idx] = (h < H_) ? (g_P[i * H_ + h] + b1p[h]) : 0.f;
    }
    for (int idx = tid; idx < 160; idx += 512) w2ps[idx] = (idx < H_) ? w2p[idx] : 0.f;

    // per-lane ldmatrix A addresses (within-buffer offsets)
    const int mgrp = wid & 7;
    const int ngrp = wid >> 3;
    uint32_t axi[2], axj[2];
    {
        const int colh = ((lane >> 4) & 1) * 16;
        #pragma unroll
        for (int t = 0; t < 2; ++t) {
            int ra = mgrp * 32 + t * 16 + (lane & 15);
            int m = ra / 50;
            int k = ra - m * 50;
            if (m > 4) { m = 4; k = 49; }   // pad rows (>=250): in-bounds garbage, masked in epilogue
            axi[t] = (uint32_t)((50 + m) * XWST + colh);
            axj[t] = (uint32_t)((m + k) * XWST + colh);
        }
    }
    const uint32_t b_off = (uint32_t)((ngrp * 80 + ((lane >> 4) & 1) * 8 + (lane & 7)) * 80
                                      + ((lane >> 3) & 1) * 16);

    float acc[2][10][4];
    #pragma unroll
    for (int t = 0; t < 2; ++t)
        #pragma unroll
        for (int nt = 0; nt < 10; ++nt)
            #pragma unroll
            for (int q = 0; q < 4; ++q) acc[t][nt][q] = 0.f;

    for (int c = 0; c < NCH; ++c) {
        if (c < NCH - 1) { CP_WAIT1(); } else { CP_WAIT0(); }
        __syncthreads();
        // issue chunk c+2 into buffer (c+2)%3 (its last reader was chunk c-1, fenced above)
        if (c + 2 < NCH) {
            int cn = c + 2, buf = cn % 3;
            cp16(dst0 + (uint32_t)buf * (uint32_t)XWSZ_OR_B(tid), src0base + cn * 64);
            if (tid < 352) cp16(dst1 + (uint32_t)buf * BSZ, src1base + cn * 64);
            CP_COMMIT();
        }
        // MMA on buffer c%3
        const int buf = c % 3;
        const uint32_t xwb = Sb + SXW + (uint32_t)buf * XWSZ;
        const uint32_t bbb = Sb + SB + (uint32_t)buf * BSZ + b_off;
        #pragma unroll
        for (int k16 = 0; k16 < 2; ++k16) {
            uint32_t a0[4], a1[4];
            {
                uint32_t xi0, xi1, xi2, xi3, xj0, xj1, xj2, xj3;
                LDSM_X4(xi0, xi1, xi2, xi3, xwb + axi[0] + k16 * 32);
                LDSM_X4(xj0, xj1, xj2, xj3, xwb + axj[0] + k16 * 32);
                a0[0] = bf2mul(xi0, xj0); a0[1] = bf2mul(xi1, xj1);
                a0[2] = bf2mul(xi2, xj2); a0[3] = bf2mul(xi3, xj3);
                LDSM_X4(xi0, xi1, xi2, xi3, xwb + axi[1] + k16 * 32);
                LDSM_X4(xj0, xj1, xj2, xj3, xwb + axj[1] + k16 * 32);
                a1[0] = bf2mul(xi0, xj0); a1[1] = bf2mul(xi1, xj1);
                a1[2] = bf2mul(xi2, xj2); a1[3] = bf2mul(xi3, xj3);
            }
            #pragma unroll
            for (int p = 0; p < 5; ++p) {
                uint32_t b0, b1, b2, b3;
                LDSM_X4(b0, b1, b2, b3, bbb + p * 1280 + k16 * 32);
                MMA16816(acc[0][2 * p],     a0[0], a0[1], a0[2], a0[3], b0, b1);
                MMA16816(acc[0][2 * p + 1], a0[0], a0[1], a0[2], a0[3], b2, b3);
                MMA16816(acc[1][2 * p],     a1[0], a1[1], a1[2], a1[3], b0, b1);
                MMA16816(acc[1][2 * p + 1], a1[0], a1[1], a1[2], a1[3], b2, b3);
            }
        }
        __syncthreads();
    }

    // ---- epilogue: per-warp 80-col partials, cross-warp combine ----
    const int g = lane >> 2, t4 = lane & 3;
    #pragma unroll
    for (int t = 0; t < 2; ++t) {
        #pragma unroll
        for (int half = 0; half < 2; ++half) {
            const int r = mgrp * 32 + t * 16 + half * 8 + g;
            float p = 0.f;
            if (r < 250) {
                const int m = r / 50, k = r - m * 50;
                const int i = i0 + m;
                const int j = i0 + m + k - K_;
                if (i < M_ && j >= 0) {
                    const float* qrow = g_Q + j * H_;
                    const float* prow = Ps + m * 160;
                    #pragma unroll
                    for (int nt = 0; nt < 10; ++nt) {
                        int hb = ngrp * 80 + nt * 8 + t4 * 2;
                        if (hb < H_) {
                            float a = acc[t][nt][half * 2]     + prow[hb]     + __ldg(qrow + hb);
                            float b = acc[t][nt][half * 2 + 1] + prow[hb + 1] + __ldg(qrow + hb + 1);
                            p += fmaxf(a, 0.f) * w2ps[hb] + fmaxf(b, 0.f) * w2ps[hb + 1];
                        }
                    }
                }
            }
            p += __shfl_xor_sync(0xffffffffu, p, 1);
            p += __shfl_xor_sync(0xffffffffu, p, 2);
            if (t4 == 0 && r < 250) part[ngrp * 256 + r] = p;
        }
    }
    __syncthreads();

    const float b2p0 = __ldg(b2p);
    if (tid < 250) {
        const int r = tid;
        const int m = r / 50, k = r - m * 50;
        const int i = i0 + m;
        const int j = i0 + m + k - K_;
        if (i < M_) {
            out[i * (K_ + 1) + k] = (j >= 0)
                ? (g_ment[i] + g_ment[j] + b2p0 + part[r] + part[256 + r]) : NEG_;
        }
    }
    if (tid >= 480 && tid < 480 + GPC) {
        int i = i0 + (tid - 480);
        if (i < M_) out[i * (K_ + 1) + K_] = 0.f;
    }
}

// ============================ launcher ============================
extern "C" void kernel_launch(void* const* d_in, const int* in_sizes, int n_in,
                              void* d_out, int out_size)
{
    const float* X   = (const float*)d_in[0];
    const float* w1m = (const float*)d_in[1];
    const float* b1m = (const float*)d_in[2];
    const float* w2m = (const float*)d_in[3];
    const float* b2m = (const float*)d_in[4];
    const float* w1p = (const float*)d_in[5];
    const float* b1p = (const float*)d_in[6];
    const float* w2p = (const float*)d_in[7];
    const float* b2p = (const float*)d_in[8];
    float* out = (float*)d_out;

    cudaFuncSetAttribute(score_mma_kernel,
                         cudaFuncAttributeMaxDynamicSharedMemorySize, SSZ);

    const int TOT = N0 + N1 + N2;
    prep_kernel<<<(TOT + 255) / 256, 256>>>(X, w1p, w1m);
    gemm_mma_kernel<<<dim3(32, 3), 256>>>();
    ment_kernel<<<M_ / 8, 256>>>(b1m, w2m, b2m);
    score_mma_kernel<<<SGRID, 512, SSZ>>>(b1p, w2p, b2p, out);
}

// round 10
// speedup vs baseline: 7.6658x; 1.0445x over previous
#include <cuda_runtime.h>
#include <cuda_bf16.h>
#include <cstdint>

#define M_ 2048
#define D_ 900
#define H_ 150
#define K_ 50
#define NEG_ (-1000000000.0f)
#define NCH 29
#define DP 928
#define XB_ROWB 1856
#define GPC 5
#define SGRID ((M_ + GPC - 1) / GPC)   // 410

// score kernel smem layout (bytes)
#define XWST 80            // X-window row stride
#define XWSZ (56 * 80)     // 4480 per buffer
#define BSZ  (160 * 80)    // 12800 per buffer
#define SXW 0              // 3 * 4480 = 13440
#define SB  13440          // 3 * 12800 = 38400
#define SPS 51840          // 5*160 f32
#define SW2 55040          // 160 f32
#define SPART 55680        // 2*256 f32
#define SSZ 57728
#define XWSZ_OR_B(t) ((t) < 224 ? XWSZ : BSZ)

// ---- scratch ----
__device__ float g_P[M_ * H_];
__device__ float g_Q[M_ * H_];
__device__ float g_ment[M_];
__device__ __align__(16) __nv_bfloat16 g_Xb[M_ * DP];
__device__ __align__(16) __nv_bfloat16 g_Wabm[480 * DP];
__device__ __align__(16) __nv_bfloat16 g_Wt[160 * DP];

// ============================ helpers ============================
__device__ __forceinline__ uint32_t smem_u32(const void* p) {
    uint32_t a;
    asm("{ .reg .u64 t; cvta.to.shared.u64 t, %1; cvt.u32.u64 %0, t; }" : "=r"(a) : "l"(p));
    return a;
}
__device__ __forceinline__ uint32_t bf2mul(uint32_t a, uint32_t b) {
    __nv_bfloat162 x, y, z;
    *(uint32_t*)&x = a; *(uint32_t*)&y = b;
    z = __hmul2(x, y);
    return *(uint32_t*)&z;
}
__device__ __forceinline__ void cp16(uint32_t dst, const void* src) {
    asm volatile("cp.async.cg.shared.global [%0], [%1], 16;" :: "r"(dst), "l"(src) : "memory");
}
#define CP_COMMIT() asm volatile("cp.async.commit_group;" ::: "memory")
#define CP_WAIT1()  asm volatile("cp.async.wait_group 1;" ::: "memory")
#define CP_WAIT0()  asm volatile("cp.async.wait_group 0;" ::: "memory")
#define CVT_BF2(res, lo, hi) asm("cvt.rn.bf16x2.f32 %0, %1, %2;" : "=r"(res) : "f"(hi), "f"(lo))
#define LDSM_X4(r0, r1, r2, r3, addr) \
    asm volatile("ldmatrix.sync.aligned.m8n8.x4.shared.b16 {%0,%1,%2,%3}, [%4];" \
        : "=r"(r0), "=r"(r1), "=r"(r2), "=r"(r3) : "r"(addr))
#define LDSM_X2(r0, r1, addr) \
    asm volatile("ldmatrix.sync.aligned.m8n8.x2.shared.b16 {%0,%1}, [%2];" \
        : "=r"(r0), "=r"(r1) : "r"(addr))
#define MMA16816(c, a0, a1, a2, a3, b0, b1) \
    asm volatile("mma.sync.aligned.m16n8k16.row.col.f32.bf16.bf16.f32 " \
        "{%0,%1,%2,%3},{%4,%5,%6,%7},{%8,%9},{%0,%1,%2,%3};" \
        : "+f"((c)[0]), "+f"((c)[1]), "+f"((c)[2]), "+f"((c)[3]) \
        : "r"(a0), "r"(a1), "r"(a2), "r"(a3), "r"(b0), "r"(b1))

// ============================ prep (8 bf16 per thread) ============================
#define N0 (M_ * DP)
#define N1 (480 * DP)
#define N2 (160 * DP)
#define TOT8 ((N0 + N1 + N2) / 8)
__global__ __launch_bounds__(256) void prep_kernel(
    const float* __restrict__ X, const float* __restrict__ w1p, const float* __restrict__ w1m)
{
    int t = blockIdx.x * 256 + threadIdx.x;
    if (t >= TOT8) return;
    int base = t * 8;
    float v[8];
    __nv_bfloat16* dst;

    if (base < N0) {
        int row = base / DP, d = base % DP;
        dst = g_Xb + base;
        if (d + 8 <= D_) {
            float4 a = __ldg((const float4*)(X + row * D_ + d));
            float4 b = __ldg((const float4*)(X + row * D_ + d + 4));
            v[0] = a.x; v[1] = a.y; v[2] = a.z; v[3] = a.w;
            v[4] = b.x; v[5] = b.y; v[6] = b.z; v[7] = b.w;
        } else {
            #pragma unroll
            for (int q = 0; q < 8; ++q)
                v[q] = (d + q < D_) ? __ldg(X + row * D_ + d + q) : 0.f;
        }
    } else if (base < N0 + N1) {
        int r = base - N0;
        int n = r / DP, d = r % DP;
        int mat = n / 160, h = n % 160;
        dst = g_Wabm + r;
        const float* src = (mat == 0) ? w1p : (mat == 1) ? (w1p + D_ * H_) : w1m;
        #pragma unroll
        for (int q = 0; q < 8; ++q)
            v[q] = (h < H_ && d + q < D_) ? __ldg(src + (d + q) * H_ + h) : 0.f;
    } else {
        int r = base - N0 - N1;
        int h = r / DP, d = r % DP;
        dst = g_Wt + r;
        const float* src = w1p + 2 * D_ * H_;
        #pragma unroll
        for (int q = 0; q < 8; ++q)
            v[q] = (h < H_ && d + q < D_) ? __ldg(src + (d + q) * H_ + h) : 0.f;
    }
    uint4 o;
    CVT_BF2(o.x, v[0], v[1]);
    CVT_BF2(o.y, v[2], v[3]);
    CVT_BF2(o.z, v[4], v[5]);
    CVT_BF2(o.w, v[6], v[7]);
    *(uint4*)dst = o;
}

// ============================ bf16 MMA GEMM for P/Q + fused ment ============================
__global__ __launch_bounds__(256) void gemm_mma_kernel(
    const float* __restrict__ b1m, const float* __restrict__ w2m, const float* __restrict__ b2m)
{
    __shared__ __align__(16) unsigned char Asm[64 * 80];
    __shared__ __align__(16) unsigned char Bsm[160 * 80];
    __shared__ float mpart[2][64];

    const int tid = threadIdx.x;
    const int wid = tid >> 5;
    const int lane = tid & 31;
    const int row0 = blockIdx.x * 64;
    const int mat = blockIdx.y;
    const char* Bsrc = (const char*)(g_Wabm + mat * 160 * DP);

    const uint32_t Ab = smem_u32(Asm);
    const uint32_t Bb = smem_u32(Bsm);
    const uint32_t a_off = Ab + (uint32_t)(((wid & 3) * 16 + (lane & 15)) * 80 + ((lane >> 4) & 1) * 16);
    const uint32_t b_off = Bb + (uint32_t)(((wid >> 2) * 80 + (lane & 7)) * 80 + ((lane >> 3) & 1) * 16);

    float acc[10][4];
    #pragma unroll
    for (int nt = 0; nt < 10; ++nt)
        #pragma unroll
        for (int q = 0; q < 4; ++q) acc[nt][q] = 0.f;

    for (int c = 0; c < NCH; ++c) {
        {
            int r = tid >> 2, grp = tid & 3;
            uint4 v = __ldg((const uint4*)((const char*)g_Xb + (row0 + r) * XB_ROWB + c * 64 + grp * 16));
            *(uint4*)(Asm + r * 80 + grp * 16) = v;
        }
        for (int idx = tid; idx < 640; idx += 256) {
            int h = idx >> 2, grp = idx & 3;
            uint4 v = __ldg((const uint4*)(Bsrc + h * XB_ROWB + c * 64 + grp * 16));
            *(uint4*)(Bsm + h * 80 + grp * 16) = v;
        }
        __syncthreads();
        #pragma unroll
        for (int k16 = 0; k16 < 2; ++k16) {
            uint32_t a0, a1, a2, a3;
            LDSM_X4(a0, a1, a2, a3, a_off + k16 * 32);
            #pragma unroll
            for (int nt = 0; nt < 10; ++nt) {
                uint32_t b0, b1;
                LDSM_X2(b0, b1, b_off + nt * 640 + k16 * 32);
                MMA16816(acc[nt], a0, a1, a2, a3, b0, b1);
            }
        }
        __syncthreads();
    }

    const int g = lane >> 2, t = lane & 3;
    const int nhalf = wid >> 2;
    if (mat < 2) {
        float* dst = (mat == 0) ? g_P : g_Q;
        #pragma unroll
        for (int nt = 0; nt < 10; ++nt) {
            int h = nhalf * 80 + nt * 8 + t * 2;
            if (h < H_) {
                int ra = row0 + (wid & 3) * 16 + g;
                dst[ra * H_ + h]           = acc[nt][0];
                dst[ra * H_ + h + 1]       = acc[nt][1];
                dst[(ra + 8) * H_ + h]     = acc[nt][2];
                dst[(ra + 8) * H_ + h + 1] = acc[nt][3];
            }
        }
    } else {
        // fused ment: relu(Hm + b1m) . w2m + b2m
        float s0 = 0.f, s1 = 0.f;
        #pragma unroll
        for (int nt = 0; nt < 10; ++nt) {
            int h = nhalf * 80 + nt * 8 + t * 2;
            if (h < H_) {
                float ba = __ldg(b1m + h), bb = __ldg(b1m + h + 1);
                float wa = __ldg(w2m + h), wb = __ldg(w2m + h + 1);
                s0 += fmaxf(acc[nt][0] + ba, 0.f) * wa + fmaxf(acc[nt][1] + bb, 0.f) * wb;
                s1 += fmaxf(acc[nt][2] + ba, 0.f) * wa + fmaxf(acc[nt][3] + bb, 0.f) * wb;
            }
        }
        s0 += __shfl_xor_sync(0xffffffffu, s0, 1);
        s0 += __shfl_xor_sync(0xffffffffu, s0, 2);
        s1 += __shfl_xor_sync(0xffffffffu, s1, 1);
        s1 += __shfl_xor_sync(0xffffffffu, s1, 2);
        int rl = (wid & 3) * 16 + g;
        if (t == 0) {
            mpart[nhalf][rl] = s0;
            mpart[nhalf][rl + 8] = s1;
        }
        __syncthreads();
        if (tid < 64)
            g_ment[row0 + tid] = mpart[0][tid] + mpart[1][tid] + __ldg(b2m);
    }
}

// ============================ score: X-window + in-register A fragments ============================
__global__ __launch_bounds__(512, 1) void score_mma_kernel(
    const float* __restrict__ b1p,
    const float* __restrict__ w2p,
    const float* __restrict__ b2p,
    float* __restrict__ out)
{
    extern __shared__ __align__(16) unsigned char sm[];
    const int tid = threadIdx.x;
    const int wid = tid >> 5;
    const int lane = tid & 31;
    const int i0 = blockIdx.x * GPC;

    float* Ps = (float*)(sm + SPS);
    float* w2ps = (float*)(sm + SW2);
    float* part = (float*)(sm + SPART);
    const uint32_t Sb = smem_u32(sm);

    // cp.async task mapping (fixed per thread)
    uint32_t dst0; const char* src0base;
    if (tid < 224) {
        int rr = tid >> 2, grp = tid & 3;
        int gr = i0 - K_ + rr;
        if (gr < 0) gr = 0; if (gr > M_ - 1) gr = M_ - 1;
        dst0 = Sb + SXW + (uint32_t)(rr * XWST + grp * 16);
        src0base = (const char*)g_Xb + gr * XB_ROWB + grp * 16;
    } else {
        int idx = tid - 224;
        int h = idx >> 2, grp = idx & 3;
        dst0 = Sb + SB + (uint32_t)(h * 80 + grp * 16);
        src0base = (const char*)g_Wt + h * XB_ROWB + grp * 16;
    }
    uint32_t dst1 = 0; const char* src1base = nullptr;
    if (tid < 352) {
        int idx = tid + 288;
        int h = idx >> 2, grp = idx & 3;
        dst1 = Sb + SB + (uint32_t)(h * 80 + grp * 16);
        src1base = (const char*)g_Wt + h * XB_ROWB + grp * 16;
    }

    // prologue: issue chunks 0 and 1
    cp16(dst0, src0base);
    if (tid < 352) cp16(dst1, src1base);
    CP_COMMIT();
    cp16(dst0 + (uint32_t)XWSZ_OR_B(tid), src0base + 64);
    if (tid < 352) cp16(dst1 + BSZ, src1base + 64);
    CP_COMMIT();

    // stage Ps / w2p
    for (int idx = tid; idx < GPC * 160; idx += 512) {
        int m = idx / 160, h = idx % 160;
        int i = i0 + m; if (i > M_ - 1) i = M_ - 1;
        Ps[idx] = (h < H_) ? (g_P[i * H_ + h] + b1p[h]) : 0.f;
    }
    for (int idx = tid; idx < 160; idx += 512) w2ps[idx] = (idx < H_) ? w2p[idx] : 0.f;

    // per-lane ldmatrix A addresses (within-buffer offsets)
    const int mgrp = wid & 7;
    const int ngrp = wid >> 3;
    uint32_t axi[2], axj[2];
    {
        const int colh = ((lane >> 4) & 1) * 16;
        #pragma unroll
        for (int t = 0; t < 2; ++t) {
            int ra = mgrp * 32 + t * 16 + (lane & 15);
            int m = ra / 50;
            int k = ra - m * 50;
            if (m > 4) { m = 4; k = 49; }
            axi[t] = (uint32_t)((50 + m) * XWST + colh);
            axj[t] = (uint32_t)((m + k) * XWST + colh);
        }
    }
    const uint32_t b_off = (uint32_t)((ngrp * 80 + ((lane >> 4) & 1) * 8 + (lane & 7)) * 80
                                      + ((lane >> 3) & 1) * 16);

    float acc[2][10][4];
    #pragma unroll
    for (int t = 0; t < 2; ++t)
        #pragma unroll
        for (int nt = 0; nt < 10; ++nt)
            #pragma unroll
            for (int q = 0; q < 4; ++q) acc[t][nt][q] = 0.f;

    for (int c = 0; c < NCH; ++c) {
        if (c < NCH - 1) { CP_WAIT1(); } else { CP_WAIT0(); }
        __syncthreads();   // all warps passed chunk c-1 MMAs; chunk c data visible
        if (c + 2 < NCH) {
            int cn = c + 2, buf = cn % 3;
            cp16(dst0 + (uint32_t)buf * (uint32_t)XWSZ_OR_B(tid), src0base + cn * 64);
            if (tid < 352) cp16(dst1 + (uint32_t)buf * BSZ, src1base + cn * 64);
            CP_COMMIT();
        }
        const int buf = c % 3;
        const uint32_t xwb = Sb + SXW + (uint32_t)buf * XWSZ;
        const uint32_t bbb = Sb + SB + (uint32_t)buf * BSZ + b_off;
        #pragma unroll
        for (int k16 = 0; k16 < 2; ++k16) {
            uint32_t a0[4], a1[4];
            {
                uint32_t xi0, xi1, xi2, xi3, xj0, xj1, xj2, xj3;
                LDSM_X4(xi0, xi1, xi2, xi3, xwb + axi[0] + k16 * 32);
                LDSM_X4(xj0, xj1, xj2, xj3, xwb + axj[0] + k16 * 32);
                a0[0] = bf2mul(xi0, xj0); a0[1] = bf2mul(xi1, xj1);
                a0[2] = bf2mul(xi2, xj2); a0[3] = bf2mul(xi3, xj3);
                LDSM_X4(xi0, xi1, xi2, xi3, xwb + axi[1] + k16 * 32);
                LDSM_X4(xj0, xj1, xj2, xj3, xwb + axj[1] + k16 * 32);
                a1[0] = bf2mul(xi0, xj0); a1[1] = bf2mul(xi1, xj1);
                a1[2] = bf2mul(xi2, xj2); a1[3] = bf2mul(xi3, xj3);
            }
            #pragma unroll
            for (int p = 0; p < 5; ++p) {
                uint32_t b0, b1, b2, b3;
                LDSM_X4(b0, b1, b2, b3, bbb + p * 1280 + k16 * 32);
                MMA16816(acc[0][2 * p],     a0[0], a0[1], a0[2], a0[3], b0, b1);
                MMA16816(acc[0][2 * p + 1], a0[0], a0[1], a0[2], a0[3], b2, b3);
                MMA16816(acc[1][2 * p],     a1[0], a1[1], a1[2], a1[3], b0, b1);
                MMA16816(acc[1][2 * p + 1], a1[0], a1[1], a1[2], a1[3], b2, b3);
            }
        }
        // no trailing barrier: next chunk's wait+bar provides the WAR fence
    }

    // ---- epilogue ----
    const int g = lane >> 2, t4 = lane & 3;
    #pragma unroll
    for (int t = 0; t < 2; ++t) {
        #pragma unroll
        for (int half = 0; half < 2; ++half) {
            const int r = mgrp * 32 + t * 16 + half * 8 + g;
            float p = 0.f;
            if (r < 250) {
                const int m = r / 50, k = r - m * 50;
                const int i = i0 + m;
                const int j = i0 + m + k - K_;
                if (i < M_ && j >= 0) {
                    const float* qrow = g_Q + j * H_;
                    const float* prow = Ps + m * 160;
                    #pragma unroll
                    for (int nt = 0; nt < 10; ++nt) {
                        int hb = ngrp * 80 + nt * 8 + t4 * 2;
                        if (hb < H_) {
                            float a = acc[t][nt][half * 2]     + prow[hb]     + __ldg(qrow + hb);
                            float b = acc[t][nt][half * 2 + 1] + prow[hb + 1] + __ldg(qrow + hb + 1);
                            p += fmaxf(a, 0.f) * w2ps[hb] + fmaxf(b, 0.f) * w2ps[hb + 1];
                        }
                    }
                }
            }
            p += __shfl_xor_sync(0xffffffffu, p, 1);
            p += __shfl_xor_sync(0xffffffffu, p, 2);
            if (t4 == 0 && r < 250) part[ngrp * 256 + r] = p;
        }
    }
    __syncthreads();

    const float b2p0 = __ldg(b2p);
    if (tid < 250) {
        const int r = tid;
        const int m = r / 50, k = r - m * 50;
        const int i = i0 + m;
        const int j = i0 + m + k - K_;
        if (i < M_) {
            out[i * (K_ + 1) + k] = (j >= 0)
                ? (g_ment[i] + g_ment[j] + b2p0 + part[r] + part[256 + r]) : NEG_;
        }
    }
    if (tid >= 480 && tid < 480 + GPC) {
        int i = i0 + (tid - 480);
        if (i < M_) out[i * (K_ + 1) + K_] = 0.f;
    }
}

// ============================ launcher ============================
extern "C" void kernel_launch(void* const* d_in, const int* in_sizes, int n_in,
                              void* d_out, int out_size)
{
    const float* X   = (const float*)d_in[0];
    const float* w1m = (const float*)d_in[1];
    const float* b1m = (const float*)d_in[2];
    const float* w2m = (const float*)d_in[3];
    const float* b2m = (const float*)d_in[4];
    const float* w1p = (const float*)d_in[5];
    const float* b1p = (const float*)d_in[6];
    const float* w2p = (const float*)d_in[7];
    const float* b2p = (const float*)d_in[8];
    float* out = (float*)d_out;

    cudaFuncSetAttribute(score_mma_kernel,
                         cudaFuncAttributeMaxDynamicSharedMemorySize, SSZ);

    prep_kernel<<<(TOT8 + 255) / 256, 256>>>(X, w1p, w1m);
    gemm_mma_kernel<<<dim3(32, 3), 256>>>(b1m, w2m, b2m);
    score_mma_kernel<<<SGRID, 512, SSZ>>>(b1p, w2p, b2p, out);
}

// round 12
// speedup vs baseline: 7.9391x; 1.0357x over previous
#include <cuda_runtime.h>
#include <cuda_bf16.h>
#include <cstdint>

#define M_ 2048
#define D_ 900
#define H_ 150
#define K_ 50
#define NEG_ (-1000000000.0f)
#define NCH 29
#define DP 928
#define XB_ROWB 1856
#define GPC 5
#define SGRID ((M_ + GPC - 1) / GPC)   // 410

// score kernel smem layout (bytes): 12-stage ring
#define NSTG 12
#define XWST 80              // X-window row stride
#define XWSZ (56 * 80)       // 4480 per stage
#define BSZ  (160 * 80)      // 12800 per stage
#define SXW 0                          // 12*4480  = 53760
#define SB  (NSTG * XWSZ)              // 53760; 12*12800 = 153600
#define SPS (SB + NSTG * BSZ)          // 207360: 5*160 f32
#define SW2 (SPS + 3200)               // 210560: 160 f32
#define SPART (SW2 + 640)              // 211200: 2*256 f32
#define SSZ (SPART + 2048)             // 213248

// ---- scratch ----
__device__ float g_P[M_ * H_];
__device__ float g_Q[M_ * H_];
__device__ float g_ment[M_];
__device__ __align__(16) __nv_bfloat16 g_Xb[M_ * DP];
__device__ __align__(16) __nv_bfloat16 g_Wabm[480 * DP];
__device__ __align__(16) __nv_bfloat16 g_Wt[160 * DP];

// ============================ helpers ============================
__device__ __forceinline__ uint32_t smem_u32(const void* p) {
    uint32_t a;
    asm("{ .reg .u64 t; cvta.to.shared.u64 t, %1; cvt.u32.u64 %0, t; }" : "=r"(a) : "l"(p));
    return a;
}
__device__ __forceinline__ uint32_t bf2mul(uint32_t a, uint32_t b) {
    __nv_bfloat162 x, y, z;
    *(uint32_t*)&x = a; *(uint32_t*)&y = b;
    z = __hmul2(x, y);
    return *(uint32_t*)&z;
}
__device__ __forceinline__ void cp16(uint32_t dst, const void* src) {
    asm volatile("cp.async.cg.shared.global [%0], [%1], 16;" :: "r"(dst), "l"(src) : "memory");
}
#define CP_COMMIT() asm volatile("cp.async.commit_group;" ::: "memory")
#define CP_WAIT1()  asm volatile("cp.async.wait_group 1;" ::: "memory")
#define CVT_BF2(res, lo, hi) asm("cvt.rn.bf16x2.f32 %0, %1, %2;" : "=r"(res) : "f"(hi), "f"(lo))
#define LDSM_X4(r0, r1, r2, r3, addr) \
    asm volatile("ldmatrix.sync.aligned.m8n8.x4.shared.b16 {%0,%1,%2,%3}, [%4];" \
        : "=r"(r0), "=r"(r1), "=r"(r2), "=r"(r3) : "r"(addr))
#define LDSM_X2(r0, r1, addr) \
    asm volatile("ldmatrix.sync.aligned.m8n8.x2.shared.b16 {%0,%1}, [%2];" \
        : "=r"(r0), "=r"(r1) : "r"(addr))
#define MMA16816(c, a0, a1, a2, a3, b0, b1) \
    asm volatile("mma.sync.aligned.m16n8k16.row.col.f32.bf16.bf16.f32 " \
        "{%0,%1,%2,%3},{%4,%5,%6,%7},{%8,%9},{%0,%1,%2,%3};" \
        : "+f"((c)[0]), "+f"((c)[1]), "+f"((c)[2]), "+f"((c)[3]) \
        : "r"(a0), "r"(a1), "r"(a2), "r"(a3), "r"(b0), "r"(b1))

// ============================ prep (8 bf16 per thread) ============================
#define N0 (M_ * DP)
#define N1 (480 * DP)
#define N2 (160 * DP)
#define TOT8 ((N0 + N1 + N2) / 8)
__global__ __launch_bounds__(256) void prep_kernel(
    const float* __restrict__ X, const float* __restrict__ w1p, const float* __restrict__ w1m)
{
    int t = blockIdx.x * 256 + threadIdx.x;
    if (t >= TOT8) return;
    int base = t * 8;
    float v[8];
    __nv_bfloat16* dst;

    if (base < N0) {
        int row = base / DP, d = base % DP;
        dst = g_Xb + base;
        if (d + 8 <= D_) {
            float4 a = __ldg((const float4*)(X + row * D_ + d));
            float4 b = __ldg((const float4*)(X + row * D_ + d + 4));
            v[0] = a.x; v[1] = a.y; v[2] = a.z; v[3] = a.w;
            v[4] = b.x; v[5] = b.y; v[6] = b.z; v[7] = b.w;
        } else {
            #pragma unroll
            for (int q = 0; q < 8; ++q)
                v[q] = (d + q < D_) ? __ldg(X + row * D_ + d + q) : 0.f;
        }
    } else if (base < N0 + N1) {
        int r = base - N0;
        int n = r / DP, d = r % DP;
        int mat = n / 160, h = n % 160;
        dst = g_Wabm + r;
        const float* src = (mat == 0) ? w1p : (mat == 1) ? (w1p + D_ * H_) : w1m;
        #pragma unroll
        for (int q = 0; q < 8; ++q)
            v[q] = (h < H_ && d + q < D_) ? __ldg(src + (d + q) * H_ + h) : 0.f;
    } else {
        int r = base - N0 - N1;
        int h = r / DP, d = r % DP;
        dst = g_Wt + r;
        const float* src = w1p + 2 * D_ * H_;
        #pragma unroll
        for (int q = 0; q < 8; ++q)
            v[q] = (h < H_ && d + q < D_) ? __ldg(src + (d + q) * H_ + h) : 0.f;
    }
    uint4 o;
    CVT_BF2(o.x, v[0], v[1]);
    CVT_BF2(o.y, v[2], v[3]);
    CVT_BF2(o.z, v[4], v[5]);
    CVT_BF2(o.w, v[6], v[7]);
    *(uint4*)dst = o;
}

// ============================ bf16 MMA GEMM for P/Q + fused ment ============================
__global__ __launch_bounds__(256) void gemm_mma_kernel(
    const float* __restrict__ b1m, const float* __restrict__ w2m, const float* __restrict__ b2m)
{
    __shared__ __align__(16) unsigned char Asm[64 * 80];
    __shared__ __align__(16) unsigned char Bsm[160 * 80];
    __shared__ float mpart[2][64];

    const int tid = threadIdx.x;
    const int wid = tid >> 5;
    const int lane = tid & 31;
    const int row0 = blockIdx.x * 64;
    const int mat = blockIdx.y;
    const char* Bsrc = (const char*)(g_Wabm + mat * 160 * DP);

    const uint32_t Ab = smem_u32(Asm);
    const uint32_t Bb = smem_u32(Bsm);
    const uint32_t a_off = Ab + (uint32_t)(((wid & 3) * 16 + (lane & 15)) * 80 + ((lane >> 4) & 1) * 16);
    const uint32_t b_off = Bb + (uint32_t)(((wid >> 2) * 80 + (lane & 7)) * 80 + ((lane >> 3) & 1) * 16);

    float acc[10][4];
    #pragma unroll
    for (int nt = 0; nt < 10; ++nt)
        #pragma unroll
        for (int q = 0; q < 4; ++q) acc[nt][q] = 0.f;

    for (int c = 0; c < NCH; ++c) {
        {
            int r = tid >> 2, grp = tid & 3;
            uint4 v = __ldg((const uint4*)((const char*)g_Xb + (row0 + r) * XB_ROWB + c * 64 + grp * 16));
            *(uint4*)(Asm + r * 80 + grp * 16) = v;
        }
        for (int idx = tid; idx < 640; idx += 256) {
            int h = idx >> 2, grp = idx & 3;
            uint4 v = __ldg((const uint4*)(Bsrc + h * XB_ROWB + c * 64 + grp * 16));
            *(uint4*)(Bsm + h * 80 + grp * 16) = v;
        }
        __syncthreads();
        #pragma unroll
        for (int k16 = 0; k16 < 2; ++k16) {
            uint32_t a0, a1, a2, a3;
            LDSM_X4(a0, a1, a2, a3, a_off + k16 * 32);
            #pragma unroll
            for (int nt = 0; nt < 10; ++nt) {
                uint32_t b0, b1;
                LDSM_X2(b0, b1, b_off + nt * 640 + k16 * 32);
                MMA16816(acc[nt], a0, a1, a2, a3, b0, b1);
            }
        }
        __syncthreads();
    }

    const int g = lane >> 2, t = lane & 3;
    const int nhalf = wid >> 2;
    if (mat < 2) {
        float* dst = (mat == 0) ? g_P : g_Q;
        #pragma unroll
        for (int nt = 0; nt < 10; ++nt) {
            int h = nhalf * 80 + nt * 8 + t * 2;
            if (h < H_) {
                int ra = row0 + (wid & 3) * 16 + g;
                dst[ra * H_ + h]           = acc[nt][0];
                dst[ra * H_ + h + 1]       = acc[nt][1];
                dst[(ra + 8) * H_ + h]     = acc[nt][2];
                dst[(ra + 8) * H_ + h + 1] = acc[nt][3];
            }
        }
    } else {
        float s0 = 0.f, s1 = 0.f;
        #pragma unroll
        for (int nt = 0; nt < 10; ++nt) {
            int h = nhalf * 80 + nt * 8 + t * 2;
            if (h < H_) {
                float ba = __ldg(b1m + h), bb = __ldg(b1m + h + 1);
                float wa = __ldg(w2m + h), wb = __ldg(w2m + h + 1);
                s0 += fmaxf(acc[nt][0] + ba, 0.f) * wa + fmaxf(acc[nt][1] + bb, 0.f) * wb;
                s1 += fmaxf(acc[nt][2] + ba, 0.f) * wa + fmaxf(acc[nt][3] + bb, 0.f) * wb;
            }
        }
        s0 += __shfl_xor_sync(0xffffffffu, s0, 1);
        s0 += __shfl_xor_sync(0xffffffffu, s0, 2);
        s1 += __shfl_xor_sync(0xffffffffu, s1, 1);
        s1 += __shfl_xor_sync(0xffffffffu, s1, 2);
        int rl = (wid & 3) * 16 + g;
        if (t == 0) {
            mpart[nhalf][rl] = s0;
            mpart[nhalf][rl + 8] = s1;
        }
        __syncthreads();
        if (tid < 64)
            g_ment[row0 + tid] = mpart[0][tid] + mpart[1][tid] + __ldg(b2m);
    }
}

// ============================ score: 12-stage ring, barrier per 4 chunks ============================
__global__ __launch_bounds__(512, 1) void score_mma_kernel(
    const float* __restrict__ b1p,
    const float* __restrict__ w2p,
    const float* __restrict__ b2p,
    float* __restrict__ out)
{
    extern __shared__ __align__(16) unsigned char sm[];
    const int tid = threadIdx.x;
    const int wid = tid >> 5;
    const int lane = tid & 31;
    const int i0 = blockIdx.x * GPC;

    float* Ps = (float*)(sm + SPS);
    float* w2ps = (float*)(sm + SW2);
    float* part = (float*)(sm + SPART);
    const uint32_t Sb = smem_u32(sm);

    // cp.async task mapping (fixed per thread)
    uint32_t dst0; const char* src0base; uint32_t st0;
    if (tid < 224) {
        int rr = tid >> 2, grp = tid & 3;
        int gr = i0 - K_ + rr;
        if (gr < 0) gr = 0; if (gr > M_ - 1) gr = M_ - 1;
        dst0 = Sb + SXW + (uint32_t)(rr * XWST + grp * 16);
        src0base = (const char*)g_Xb + gr * XB_ROWB + grp * 16;
        st0 = XWSZ;
    } else {
        int idx = tid - 224;
        int h = idx >> 2, grp = idx & 3;
        dst0 = Sb + SB + (uint32_t)(h * 80 + grp * 16);
        src0base = (const char*)g_Wt + h * XB_ROWB + grp * 16;
        st0 = BSZ;
    }
    uint32_t dst1 = 0; const char* src1base = nullptr;
    if (tid < 352) {
        int idx = tid + 288;
        int h = idx >> 2, grp = idx & 3;
        dst1 = Sb + SB + (uint32_t)(h * 80 + grp * 16);
        src1base = (const char*)g_Wt + h * XB_ROWB + grp * 16;
    }

    // prologue: chunks 0..3 (group 1), 4..7 (group 2); stages = chunk (0..7 < 12)
    #pragma unroll
    for (int cn = 0; cn < 4; ++cn) {
        cp16(dst0 + (uint32_t)cn * st0, src0base + cn * 64);
        if (tid < 352) cp16(dst1 + (uint32_t)cn * BSZ, src1base + cn * 64);
    }
    CP_COMMIT();
    #pragma unroll
    for (int cn = 4; cn < 8; ++cn) {
        cp16(dst0 + (uint32_t)cn * st0, src0base + cn * 64);
        if (tid < 352) cp16(dst1 + (uint32_t)cn * BSZ, src1base + cn * 64);
    }
    CP_COMMIT();

    // stage Ps / w2p
    for (int idx = tid; idx < GPC * 160; idx += 512) {
        int m = idx / 160, h = idx % 160;
        int i = i0 + m; if (i > M_ - 1) i = M_ - 1;
        Ps[idx] = (h < H_) ? (g_P[i * H_ + h] + b1p[h]) : 0.f;
    }
    for (int idx = tid; idx < 160; idx += 512) w2ps[idx] = (idx < H_) ? w2p[idx] : 0.f;

    // per-lane ldmatrix A addresses (within-stage offsets)
    const int mgrp = wid & 7;
    const int ngrp = wid >> 3;
    uint32_t axi[2], axj[2];
    {
        const int colh = ((lane >> 4) & 1) * 16;
        #pragma unroll
        for (int t = 0; t < 2; ++t) {
            int ra = mgrp * 32 + t * 16 + (lane & 15);
            int m = ra / 50;
            int k = ra - m * 50;
            if (m > 4) { m = 4; k = 49; }
            axi[t] = (uint32_t)((50 + m) * XWST + colh);
            axj[t] = (uint32_t)((m + k) * XWST + colh);
        }
    }
    const uint32_t b_off = (uint32_t)((ngrp * 80 + ((lane >> 4) & 1) * 8 + (lane & 7)) * 80
                                      + ((lane >> 3) & 1) * 16);

    float acc[2][10][4];
    #pragma unroll
    for (int t = 0; t < 2; ++t)
        #pragma unroll
        for (int nt = 0; nt < 10; ++nt)
            #pragma unroll
            for (int q = 0; q < 4; ++q) acc[t][nt][q] = 0.f;

    // main loop: 8 periods of 4 chunks
    for (int p = 0; p < 8; ++p) {
        CP_WAIT1();          // retires group from period p-2 == this period's chunks
        __syncthreads();     // publish fills + fence last period's reads (WAR)
        // issue fills for chunks 4p+8 .. 4p+11
        #pragma unroll
        for (int q = 0; q < 4; ++q) {
            int cn = 4 * p + 8 + q;
            if (cn < NCH) {
                uint32_t stg = (uint32_t)(cn % NSTG);
                cp16(dst0 + stg * st0, src0base + cn * 64);
                if (tid < 352) cp16(dst1 + stg * BSZ, src1base + cn * 64);
            }
        }
        CP_COMMIT();         // empty group ok for late periods
        // MMA on chunks 4p .. 4p+3 (stages c%12) — no barriers between chunks
        #pragma unroll
        for (int q = 0; q < 4; ++q) {
            int c = 4 * p + q;
            if (c < NCH) {
                uint32_t stg = (uint32_t)(c % NSTG);
                const uint32_t xwb = Sb + SXW + stg * XWSZ;
                const uint32_t bbb = Sb + SB + stg * BSZ + b_off;
                #pragma unroll
                for (int k16 = 0; k16 < 2; ++k16) {
                    uint32_t a0[4], a1[4];
                    {
                        uint32_t xi0, xi1, xi2, xi3, xj0, xj1, xj2, xj3;
                        LDSM_X4(xi0, xi1, xi2, xi3, xwb + axi[0] + k16 * 32);
                        LDSM_X4(xj0, xj1, xj2, xj3, xwb + axj[0] + k16 * 32);
                        a0[0] = bf2mul(xi0, xj0); a0[1] = bf2mul(xi1, xj1);
                        a0[2] = bf2mul(xi2, xj2); a0[3] = bf2mul(xi3, xj3);
                        LDSM_X4(xi0, xi1, xi2, xi3, xwb + axi[1] + k16 * 32);
                        LDSM_X4(xj0, xj1, xj2, xj3, xwb + axj[1] + k16 * 32);
                        a1[0] = bf2mul(xi0, xj0); a1[1] = bf2mul(xi1, xj1);
                        a1[2] = bf2mul(xi2, xj2); a1[3] = bf2mul(xi3, xj3);
                    }
                    #pragma unroll
                    for (int pp = 0; pp < 5; ++pp) {
                        uint32_t b0, b1, b2, b3;
                        LDSM_X4(b0, b1, b2, b3, bbb + pp * 1280 + k16 * 32);
                        MMA16816(acc[0][2 * pp],     a0[0], a0[1], a0[2], a0[3], b0, b1);
                        MMA16816(acc[0][2 * pp + 1], a0[0], a0[1], a0[2], a0[3], b2, b3);
                        MMA16816(acc[1][2 * pp],     a1[0], a1[1], a1[2], a1[3], b0, b1);
                        MMA16816(acc[1][2 * pp + 1], a1[0], a1[1], a1[2], a1[3], b2, b3);
                    }
                }
            }
        }
    }

    // ---- epilogue ----
    const int g = lane >> 2, t4 = lane & 3;
    #pragma unroll
    for (int t = 0; t < 2; ++t) {
        #pragma unroll
        for (int half = 0; half < 2; ++half) {
            const int r = mgrp * 32 + t * 16 + half * 8 + g;
            float p = 0.f;
            if (r < 250) {
                const int m = r / 50, k = r - m * 50;
                const int i = i0 + m;
                const int j = i0 + m + k - K_;
                if (i < M_ && j >= 0) {
                    const float* qrow = g_Q + j * H_;
                    const float* prow = Ps + m * 160;
                    #pragma unroll
                    for (int nt = 0; nt < 10; ++nt) {
                        int hb = ngrp * 80 + nt * 8 + t4 * 2;
                        if (hb < H_) {
                            float a = acc[t][nt][half * 2]     + prow[hb]     + __ldg(qrow + hb);
                            float b = acc[t][nt][half * 2 + 1] + prow[hb + 1] + __ldg(qrow + hb + 1);
                            p += fmaxf(a, 0.f) * w2ps[hb] + fmaxf(b, 0.f) * w2ps[hb + 1];
                        }
                    }
                }
            }
            p += __shfl_xor_sync(0xffffffffu, p, 1);
            p += __shfl_xor_sync(0xffffffffu, p, 2);
            if (t4 == 0 && r < 250) part[ngrp * 256 + r] = p;
        }
    }
    __syncthreads();

    const float b2p0 = __ldg(b2p);
    if (tid < 250) {
        const int r = tid;
        const int m = r / 50, k = r - m * 50;
        const int i = i0 + m;
        const int j = i0 + m + k - K_;
        if (i < M_) {
            out[i * (K_ + 1) + k] = (j >= 0)
                ? (g_ment[i] + g_ment[j] + b2p0 + part[r] + part[256 + r]) : NEG_;
        }
    }
    if (tid >= 480 && tid < 480 + GPC) {
        int i = i0 + (tid - 480);
        if (i < M_) out[i * (K_ + 1) + K_] = 0.f;
    }
}

// ============================ launcher ============================
extern "C" void kernel_launch(void* const* d_in, const int* in_sizes, int n_in,
                              void* d_out, int out_size)
{
    const float* X   = (const float*)d_in[0];
    const float* w1m = (const float*)d_in[1];
    const float* b1m = (const float*)d_in[2];
    const float* w2m = (const float*)d_in[3];
    const float* b2m = (const float*)d_in[4];
    const float* w1p = (const float*)d_in[5];
    const float* b1p = (const float*)d_in[6];
    const float* w2p = (const float*)d_in[7];
    const float* b2p = (const float*)d_in[8];
    float* out = (float*)d_out;

    cudaFuncSetAttribute(score_mma_kernel,
                         cudaFuncAttributeMaxDynamicSharedMemorySize, SSZ);

    prep_kernel<<<(TOT8 + 255) / 256, 256>>>(X, w1p, w1m);
    gemm_mma_kernel<<<dim3(32, 3), 256>>>(b1m, w2m, b2m);
    score_mma_kernel<<<SGRID, 512, SSZ>>>(b1p, w2p, b2p, out);
}

// round 13
// speedup vs baseline: 8.1448x; 1.0259x over previous
#include <cuda_runtime.h>
#include <cuda_bf16.h>
#include <cstdint>

#define M_ 2048
#define D_ 900
#define H_ 150
#define K_ 50
#define NEG_ (-1000000000.0f)
#define NCH 29
#define DP 928
#define XB_ROWB 1856
#define GPC 5
#define SGRID ((M_ + GPC - 1) / GPC)   // 410

// score kernel smem layout (bytes): 12-stage ring
#define NSTG 12
#define XWST 80              // X-window row stride
#define XWSZ (56 * 80)       // 4480 per stage
#define BSZ  (160 * 80)      // 12800 per stage
#define SXW 0                          // 12*4480  = 53760
#define SB  (NSTG * XWSZ)              // 53760; 12*12800 = 153600
#define SPS (SB + NSTG * BSZ)          // 207360: 5*160 f32
#define SW2 (SPS + 3200)               // 210560: 160 f32
#define SPART (SW2 + 640)              // 211200: 2*256 f32
#define SSZ (SPART + 2048)             // 213248

// ---- scratch ----
__device__ float g_P[M_ * H_];
__device__ float g_Q[M_ * H_];
__device__ float g_ment[M_];
__device__ __align__(16) __nv_bfloat16 g_Xb[M_ * DP];
__device__ __align__(16) __nv_bfloat16 g_Wabm[480 * DP];
__device__ __align__(16) __nv_bfloat16 g_Wt[160 * DP];

// ============================ helpers ============================
__device__ __forceinline__ uint32_t smem_u32(const void* p) {
    uint32_t a;
    asm("{ .reg .u64 t; cvta.to.shared.u64 t, %1; cvt.u32.u64 %0, t; }" : "=r"(a) : "l"(p));
    return a;
}
__device__ __forceinline__ uint32_t bf2mul(uint32_t a, uint32_t b) {
    __nv_bfloat162 x, y, z;
    *(uint32_t*)&x = a; *(uint32_t*)&y = b;
    z = __hmul2(x, y);
    return *(uint32_t*)&z;
}
__device__ __forceinline__ void cp16(uint32_t dst, const void* src) {
    asm volatile("cp.async.cg.shared.global [%0], [%1], 16;" :: "r"(dst), "l"(src) : "memory");
}
#define CP_COMMIT() asm volatile("cp.async.commit_group;" ::: "memory")
#define CP_WAIT1()  asm volatile("cp.async.wait_group 1;" ::: "memory")
#define CVT_BF2(res, lo, hi) asm("cvt.rn.bf16x2.f32 %0, %1, %2;" : "=r"(res) : "f"(hi), "f"(lo))
#define LDSM_X4(r0, r1, r2, r3, addr) \
    asm volatile("ldmatrix.sync.aligned.m8n8.x4.shared.b16 {%0,%1,%2,%3}, [%4];" \
        : "=r"(r0), "=r"(r1), "=r"(r2), "=r"(r3) : "r"(addr))
#define LDSM_X2(r0, r1, addr) \
    asm volatile("ldmatrix.sync.aligned.m8n8.x2.shared.b16 {%0,%1}, [%2];" \
        : "=r"(r0), "=r"(r1) : "r"(addr))
#define MMA16816(c, a0, a1, a2, a3, b0, b1) \
    asm volatile("mma.sync.aligned.m16n8k16.row.col.f32.bf16.bf16.f32 " \
        "{%0,%1,%2,%3},{%4,%5,%6,%7},{%8,%9},{%0,%1,%2,%3};" \
        : "+f"((c)[0]), "+f"((c)[1]), "+f"((c)[2]), "+f"((c)[3]) \
        : "r"(a0), "r"(a1), "r"(a2), "r"(a3), "r"(b0), "r"(b1))

// ============================ prep (8 bf16 per thread) ============================
#define N0 (M_ * DP)
#define N1 (480 * DP)
#define N2 (160 * DP)
#define TOT8 ((N0 + N1 + N2) / 8)
__global__ __launch_bounds__(256) void prep_kernel(
    const float* __restrict__ X, const float* __restrict__ w1p, const float* __restrict__ w1m)
{
    int t = blockIdx.x * 256 + threadIdx.x;
    if (t >= TOT8) return;
    int base = t * 8;
    float v[8];
    __nv_bfloat16* dst;

    if (base < N0) {
        int row = base / DP, d = base % DP;
        dst = g_Xb + base;
        if (d + 8 <= D_) {
            float4 a = __ldg((const float4*)(X + row * D_ + d));
            float4 b = __ldg((const float4*)(X + row * D_ + d + 4));
            v[0] = a.x; v[1] = a.y; v[2] = a.z; v[3] = a.w;
            v[4] = b.x; v[5] = b.y; v[6] = b.z; v[7] = b.w;
        } else {
            #pragma unroll
            for (int q = 0; q < 8; ++q)
                v[q] = (d + q < D_) ? __ldg(X + row * D_ + d + q) : 0.f;
        }
    } else if (base < N0 + N1) {
        int r = base - N0;
        int n = r / DP, d = r % DP;
        int mat = n / 160, h = n % 160;
        dst = g_Wabm + r;
        const float* src = (mat == 0) ? w1p : (mat == 1) ? (w1p + D_ * H_) : w1m;
        #pragma unroll
        for (int q = 0; q < 8; ++q)
            v[q] = (h < H_ && d + q < D_) ? __ldg(src + (d + q) * H_ + h) : 0.f;
    } else {
        int r = base - N0 - N1;
        int h = r / DP, d = r % DP;
        dst = g_Wt + r;
        const float* src = w1p + 2 * D_ * H_;
        #pragma unroll
        for (int q = 0; q < 8; ++q)
            v[q] = (h < H_ && d + q < D_) ? __ldg(src + (d + q) * H_ + h) : 0.f;
    }
    uint4 o;
    CVT_BF2(o.x, v[0], v[1]);
    CVT_BF2(o.y, v[2], v[3]);
    CVT_BF2(o.z, v[4], v[5]);
    CVT_BF2(o.w, v[6], v[7]);
    *(uint4*)dst = o;
}

// ============================ bf16 MMA GEMM for P/Q + fused ment (M=32 tiles) ============================
// grid (64, 3), 256 threads. Warp w: rows (w&1)*16 .. +15, cols (w>>1)*40 .. +39 (5 n8-tiles).
__global__ __launch_bounds__(256) void gemm_mma_kernel(
    const float* __restrict__ b1m, const float* __restrict__ w2m, const float* __restrict__ b2m)
{
    __shared__ __align__(16) unsigned char Asm[32 * 80];
    __shared__ __align__(16) unsigned char Bsm[160 * 80];
    __shared__ float mpart[4][32];

    const int tid = threadIdx.x;
    const int wid = tid >> 5;
    const int lane = tid & 31;
    const int row0 = blockIdx.x * 32;
    const int mat = blockIdx.y;
    const char* Bsrc = (const char*)(g_Wabm + mat * 160 * DP);

    const int mhalf = wid & 1;
    const int ngrp4 = wid >> 1;

    const uint32_t Ab = smem_u32(Asm);
    const uint32_t Bb = smem_u32(Bsm);
    const uint32_t a_off = Ab + (uint32_t)((mhalf * 16 + (lane & 15)) * 80 + ((lane >> 4) & 1) * 16);
    const uint32_t b_off = Bb + (uint32_t)((ngrp4 * 40 + (lane & 7)) * 80 + ((lane >> 3) & 1) * 16);

    float acc[5][4];
    #pragma unroll
    for (int nt = 0; nt < 5; ++nt)
        #pragma unroll
        for (int q = 0; q < 4; ++q) acc[nt][q] = 0.f;

    for (int c = 0; c < NCH; ++c) {
        if (tid < 128) {
            int r = tid >> 2, grp = tid & 3;
            uint4 v = __ldg((const uint4*)((const char*)g_Xb + (row0 + r) * XB_ROWB + c * 64 + grp * 16));
            *(uint4*)(Asm + r * 80 + grp * 16) = v;
        }
        for (int idx = tid; idx < 640; idx += 256) {
            int h = idx >> 2, grp = idx & 3;
            uint4 v = __ldg((const uint4*)(Bsrc + h * XB_ROWB + c * 64 + grp * 16));
            *(uint4*)(Bsm + h * 80 + grp * 16) = v;
        }
        __syncthreads();
        #pragma unroll
        for (int k16 = 0; k16 < 2; ++k16) {
            uint32_t a0, a1, a2, a3;
            LDSM_X4(a0, a1, a2, a3, a_off + k16 * 32);
            #pragma unroll
            for (int nt = 0; nt < 5; ++nt) {
                uint32_t b0, b1;
                LDSM_X2(b0, b1, b_off + nt * 640 + k16 * 32);
                MMA16816(acc[nt], a0, a1, a2, a3, b0, b1);
            }
        }
        __syncthreads();
    }

    const int g = lane >> 2, t = lane & 3;
    if (mat < 2) {
        float* dst = (mat == 0) ? g_P : g_Q;
        #pragma unroll
        for (int nt = 0; nt < 5; ++nt) {
            int h = ngrp4 * 40 + nt * 8 + t * 2;
            if (h < H_) {
                int ra = row0 + mhalf * 16 + g;
                dst[ra * H_ + h]           = acc[nt][0];
                dst[ra * H_ + h + 1]       = acc[nt][1];
                dst[(ra + 8) * H_ + h]     = acc[nt][2];
                dst[(ra + 8) * H_ + h + 1] = acc[nt][3];
            }
        }
    } else {
        float s0 = 0.f, s1 = 0.f;
        #pragma unroll
        for (int nt = 0; nt < 5; ++nt) {
            int h = ngrp4 * 40 + nt * 8 + t * 2;
            if (h < H_) {
                float ba = __ldg(b1m + h), bb = __ldg(b1m + h + 1);
                float wa = __ldg(w2m + h), wb = __ldg(w2m + h + 1);
                s0 += fmaxf(acc[nt][0] + ba, 0.f) * wa + fmaxf(acc[nt][1] + bb, 0.f) * wb;
                s1 += fmaxf(acc[nt][2] + ba, 0.f) * wa + fmaxf(acc[nt][3] + bb, 0.f) * wb;
            }
        }
        s0 += __shfl_xor_sync(0xffffffffu, s0, 1);
        s0 += __shfl_xor_sync(0xffffffffu, s0, 2);
        s1 += __shfl_xor_sync(0xffffffffu, s1, 1);
        s1 += __shfl_xor_sync(0xffffffffu, s1, 2);
        int rl = mhalf * 16 + g;
        if (t == 0) {
            mpart[ngrp4][rl] = s0;
            mpart[ngrp4][rl + 8] = s1;
        }
        __syncthreads();
        if (tid < 32)
            g_ment[row0 + tid] = mpart[0][tid] + mpart[1][tid] + mpart[2][tid] + mpart[3][tid]
                                 + __ldg(b2m);
    }
}

// ============================ score: 12-stage ring + B-fragment prefetch ============================
__global__ __launch_bounds__(512, 1) void score_mma_kernel(
    const float* __restrict__ b1p,
    const float* __restrict__ w2p,
    const float* __restrict__ b2p,
    float* __restrict__ out)
{
    extern __shared__ __align__(16) unsigned char sm[];
    const int tid = threadIdx.x;
    const int wid = tid >> 5;
    const int lane = tid & 31;
    const int i0 = blockIdx.x * GPC;

    float* Ps = (float*)(sm + SPS);
    float* w2ps = (float*)(sm + SW2);
    float* part = (float*)(sm + SPART);
    const uint32_t Sb = smem_u32(sm);

    // cp.async task mapping (fixed per thread)
    uint32_t dst0; const char* src0base; uint32_t st0;
    if (tid < 224) {
        int rr = tid >> 2, grp = tid & 3;
        int gr = i0 - K_ + rr;
        if (gr < 0) gr = 0; if (gr > M_ - 1) gr = M_ - 1;
        dst0 = Sb + SXW + (uint32_t)(rr * XWST + grp * 16);
        src0base = (const char*)g_Xb + gr * XB_ROWB + grp * 16;
        st0 = XWSZ;
    } else {
        int idx = tid - 224;
        int h = idx >> 2, grp = idx & 3;
        dst0 = Sb + SB + (uint32_t)(h * 80 + grp * 16);
        src0base = (const char*)g_Wt + h * XB_ROWB + grp * 16;
        st0 = BSZ;
    }
    uint32_t dst1 = 0; const char* src1base = nullptr;
    if (tid < 352) {
        int idx = tid + 288;
        int h = idx >> 2, grp = idx & 3;
        dst1 = Sb + SB + (uint32_t)(h * 80 + grp * 16);
        src1base = (const char*)g_Wt + h * XB_ROWB + grp * 16;
    }

    // prologue: chunks 0..3 (group 1), 4..7 (group 2)
    #pragma unroll
    for (int cn = 0; cn < 4; ++cn) {
        cp16(dst0 + (uint32_t)cn * st0, src0base + cn * 64);
        if (tid < 352) cp16(dst1 + (uint32_t)cn * BSZ, src1base + cn * 64);
    }
    CP_COMMIT();
    #pragma unroll
    for (int cn = 4; cn < 8; ++cn) {
        cp16(dst0 + (uint32_t)cn * st0, src0base + cn * 64);
        if (tid < 352) cp16(dst1 + (uint32_t)cn * BSZ, src1base + cn * 64);
    }
    CP_COMMIT();

    // stage Ps / w2p
    for (int idx = tid; idx < GPC * 160; idx += 512) {
        int m = idx / 160, h = idx % 160;
        int i = i0 + m; if (i > M_ - 1) i = M_ - 1;
        Ps[idx] = (h < H_) ? (g_P[i * H_ + h] + b1p[h]) : 0.f;
    }
    for (int idx = tid; idx < 160; idx += 512) w2ps[idx] = (idx < H_) ? w2p[idx] : 0.f;

    // per-lane ldmatrix A addresses (within-stage offsets)
    const int mgrp = wid & 7;
    const int ngrp = wid >> 3;
    uint32_t axi[2], axj[2];
    {
        const int colh = ((lane >> 4) & 1) * 16;
        #pragma unroll
        for (int t = 0; t < 2; ++t) {
            int ra = mgrp * 32 + t * 16 + (lane & 15);
            int m = ra / 50;
            int k = ra - m * 50;
            if (m > 4) { m = 4; k = 49; }
            axi[t] = (uint32_t)((50 + m) * XWST + colh);
            axj[t] = (uint32_t)((m + k) * XWST + colh);
        }
    }
    const uint32_t b_off = (uint32_t)((ngrp * 80 + ((lane >> 4) & 1) * 8 + (lane & 7)) * 80
                                      + ((lane >> 3) & 1) * 16);

    float acc[2][10][4];
    #pragma unroll
    for (int t = 0; t < 2; ++t)
        #pragma unroll
        for (int nt = 0; nt < 10; ++nt)
            #pragma unroll
            for (int q = 0; q < 4; ++q) acc[t][nt][q] = 0.f;

    // main loop: 8 periods of 4 chunks
    for (int p = 0; p < 8; ++p) {
        CP_WAIT1();
        __syncthreads();
        #pragma unroll
        for (int q = 0; q < 4; ++q) {
            int cn = 4 * p + 8 + q;
            if (cn < NCH) {
                uint32_t stg = (uint32_t)(cn % NSTG);
                cp16(dst0 + stg * st0, src0base + cn * 64);
                if (tid < 352) cp16(dst1 + stg * BSZ, src1base + cn * 64);
            }
        }
        CP_COMMIT();
        #pragma unroll
        for (int q = 0; q < 4; ++q) {
            int c = 4 * p + q;
            if (c < NCH) {
                uint32_t stg = (uint32_t)(c % NSTG);
                const uint32_t xwb = Sb + SXW + stg * XWSZ;
                const uint32_t bbb = Sb + SB + stg * BSZ + b_off;
                #pragma unroll
                for (int k16 = 0; k16 < 2; ++k16) {
                    uint32_t a0[4], a1[4];
                    {
                        uint32_t xi0, xi1, xi2, xi3, xj0, xj1, xj2, xj3;
                        LDSM_X4(xi0, xi1, xi2, xi3, xwb + axi[0] + k16 * 32);
                        LDSM_X4(xj0, xj1, xj2, xj3, xwb + axj[0] + k16 * 32);
                        a0[0] = bf2mul(xi0, xj0); a0[1] = bf2mul(xi1, xj1);
                        a0[2] = bf2mul(xi2, xj2); a0[3] = bf2mul(xi3, xj3);
                        LDSM_X4(xi0, xi1, xi2, xi3, xwb + axi[1] + k16 * 32);
                        LDSM_X4(xj0, xj1, xj2, xj3, xwb + axj[1] + k16 * 32);
                        a1[0] = bf2mul(xi0, xj0); a1[1] = bf2mul(xi1, xj1);
                        a1[2] = bf2mul(xi2, xj2); a1[3] = bf2mul(xi3, xj3);
                    }
                    // B-fragment pipeline: prefetch pp+1 before MMAs of pp
                    uint32_t bc0, bc1, bc2, bc3;
                    LDSM_X4(bc0, bc1, bc2, bc3, bbb + k16 * 32);
                    #pragma unroll
                    for (int pp = 0; pp < 5; ++pp) {
                        uint32_t bn0, bn1, bn2, bn3;
                        if (pp < 4) LDSM_X4(bn0, bn1, bn2, bn3, bbb + (pp + 1) * 1280 + k16 * 32);
                        MMA16816(acc[0][2 * pp],     a0[0], a0[1], a0[2], a0[3], bc0, bc1);
                        MMA16816(acc[0][2 * pp + 1], a0[0], a0[1], a0[2], a0[3], bc2, bc3);
                        MMA16816(acc[1][2 * pp],     a1[0], a1[1], a1[2], a1[3], bc0, bc1);
                        MMA16816(acc[1][2 * pp + 1], a1[0], a1[1], a1[2], a1[3], bc2, bc3);
                        if (pp < 4) { bc0 = bn0; bc1 = bn1; bc2 = bn2; bc3 = bn3; }
                    }
                }
            }
        }
    }

    // ---- epilogue ----
    const int g = lane >> 2, t4 = lane & 3;
    #pragma unroll
    for (int t = 0; t < 2; ++t) {
        #pragma unroll
        for (int half = 0; half < 2; ++half) {
            const int r = mgrp * 32 + t * 16 + half * 8 + g;
            float p = 0.f;
            if (r < 250) {
                const int m = r / 50, k = r - m * 50;
                const int i = i0 + m;
                const int j = i0 + m + k - K_;
                if (i < M_ && j >= 0) {
                    const float* qrow = g_Q + j * H_;
                    const float* prow = Ps + m * 160;
                    #pragma unroll
                    for (int nt = 0; nt < 10; ++nt) {
                        int hb = ngrp * 80 + nt * 8 + t4 * 2;
                        if (hb < H_) {
                            float a = acc[t][nt][half * 2]     + prow[hb]     + __ldg(qrow + hb);
                            float b = acc[t][nt][half * 2 + 1] + prow[hb + 1] + __ldg(qrow + hb + 1);
                            p += fmaxf(a, 0.f) * w2ps[hb] + fmaxf(b, 0.f) * w2ps[hb + 1];
                        }
                    }
                }
            }
            p += __shfl_xor_sync(0xffffffffu, p, 1);
            p += __shfl_xor_sync(0xffffffffu, p, 2);
            if (t4 == 0 && r < 250) part[ngrp * 256 + r] = p;
        }
    }
    __syncthreads();

    const float b2p0 = __ldg(b2p);
    if (tid < 250) {
        const int r = tid;
        const int m = r / 50, k = r - m * 50;
        const int i = i0 + m;
        const int j = i0 + m + k - K_;
        if (i < M_) {
            out[i * (K_ + 1) + k] = (j >= 0)
                ? (g_ment[i] + g_ment[j] + b2p0 + part[r] + part[256 + r]) : NEG_;
        }
    }
    if (tid >= 480 && tid < 480 + GPC) {
        int i = i0 + (tid - 480);
        if (i < M_) out[i * (K_ + 1) + K_] = 0.f;
    }
}

// ============================ launcher ============================
extern "C" void kernel_launch(void* const* d_in, const int* in_sizes, int n_in,
                              void* d_out, int out_size)
{
    const float* X   = (const float*)d_in[0];
    const float* w1m = (const float*)d_in[1];
    const float* b1m = (const float*)d_in[2];
    const float* w2m = (const float*)d_in[3];
    const float* b2m = (const float*)d_in[4];
    const float* w1p = (const float*)d_in[5];
    const float* b1p = (const float*)d_in[6];
    const float* w2p = (const float*)d_in[7];
    const float* b2p = (const float*)d_in[8];
    float* out = (float*)d_out;

    cudaFuncSetAttribute(score_mma_kernel,
                         cudaFuncAttributeMaxDynamicSharedMemorySize, SSZ);

    prep_kernel<<<(TOT8 + 255) / 256, 256>>>(X, w1p, w1m);
    gemm_mma_kernel<<<dim3(64, 3), 256>>>(b1m, w2m, b2m);
    score_mma_kernel<<<SGRID, 512, SSZ>>>(b1p, w2p, b2p, out);
}

// round 14
// speedup vs baseline: 8.6736x; 1.0649x over previous
#include <cuda_runtime.h>
#include <cuda_bf16.h>
#include <cstdint>

#define M_ 2048
#define D_ 900
#define H_ 150
#define K_ 50
#define NEG_ (-1000000000.0f)
#define NCH 29
#define DP 928
#define XB_ROWB 1856
#define GPC 5
#define SGRID ((M_ + GPC - 1) / GPC)   // 410

// score kernel smem (bytes): 8-stage ring, N-split CTA (80 cols)
#define NSTG 8
#define XWST 80
#define XWSZ (56 * 80)       // 4480
#define BSZ  (80 * 80)       // 6400
#define SXW 0                //  8*4480 = 35840
#define SB  35840            //  8*6400 = 51200 -> 87040
#define SPS 87040            //  5*80 f32 = 1600
#define SW2 88640            //  80 f32 = 320
#define SSZ 88960

// ---- scratch ----
__device__ float g_P[M_ * H_];
__device__ float g_Q[M_ * H_];
__device__ float g_ment[M_];
__device__ float g_sp[2][M_ * K_];
__device__ __align__(16) __nv_bfloat16 g_Xb[M_ * DP];
__device__ __align__(16) __nv_bfloat16 g_Wabm[480 * DP];
__device__ __align__(16) __nv_bfloat16 g_Wt[160 * DP];

// ============================ helpers ============================
__device__ __forceinline__ uint32_t smem_u32(const void* p) {
    uint32_t a;
    asm("{ .reg .u64 t; cvta.to.shared.u64 t, %1; cvt.u32.u64 %0, t; }" : "=r"(a) : "l"(p));
    return a;
}
__device__ __forceinline__ uint32_t bf2mul(uint32_t a, uint32_t b) {
    __nv_bfloat162 x, y, z;
    *(uint32_t*)&x = a; *(uint32_t*)&y = b;
    z = __hmul2(x, y);
    return *(uint32_t*)&z;
}
__device__ __forceinline__ void cp16(uint32_t dst, const void* src) {
    asm volatile("cp.async.cg.shared.global [%0], [%1], 16;" :: "r"(dst), "l"(src) : "memory");
}
#define CP_COMMIT() asm volatile("cp.async.commit_group;" ::: "memory")
#define CP_WAIT1()  asm volatile("cp.async.wait_group 1;" ::: "memory")
#define CVT_BF2(res, lo, hi) asm("cvt.rn.bf16x2.f32 %0, %1, %2;" : "=r"(res) : "f"(hi), "f"(lo))
#define LDSM_X4(r0, r1, r2, r3, addr) \
    asm volatile("ldmatrix.sync.aligned.m8n8.x4.shared.b16 {%0,%1,%2,%3}, [%4];" \
        : "=r"(r0), "=r"(r1), "=r"(r2), "=r"(r3) : "r"(addr))
#define LDSM_X2(r0, r1, addr) \
    asm volatile("ldmatrix.sync.aligned.m8n8.x2.shared.b16 {%0,%1}, [%2];" \
        : "=r"(r0), "=r"(r1) : "r"(addr))
#define MMA16816(c, a0, a1, a2, a3, b0, b1) \
    asm volatile("mma.sync.aligned.m16n8k16.row.col.f32.bf16.bf16.f32 " \
        "{%0,%1,%2,%3},{%4,%5,%6,%7},{%8,%9},{%0,%1,%2,%3};" \
        : "+f"((c)[0]), "+f"((c)[1]), "+f"((c)[2]), "+f"((c)[3]) \
        : "r"(a0), "r"(a1), "r"(a2), "r"(a3), "r"(b0), "r"(b1))

// ============================ prep (8 bf16 per thread) ============================
#define N0 (M_ * DP)
#define N1 (480 * DP)
#define N2 (160 * DP)
#define TOT8 ((N0 + N1 + N2) / 8)
__global__ __launch_bounds__(256) void prep_kernel(
    const float* __restrict__ X, const float* __restrict__ w1p, const float* __restrict__ w1m)
{
    int t = blockIdx.x * 256 + threadIdx.x;
    if (t >= TOT8) return;
    int base = t * 8;
    float v[8];
    __nv_bfloat16* dst;

    if (base < N0) {
        int row = base / DP, d = base % DP;
        dst = g_Xb + base;
        if (d + 8 <= D_) {
            float4 a = __ldg((const float4*)(X + row * D_ + d));
            float4 b = __ldg((const float4*)(X + row * D_ + d + 4));
            v[0] = a.x; v[1] = a.y; v[2] = a.z; v[3] = a.w;
            v[4] = b.x; v[5] = b.y; v[6] = b.z; v[7] = b.w;
        } else {
            #pragma unroll
            for (int q = 0; q < 8; ++q)
                v[q] = (d + q < D_) ? __ldg(X + row * D_ + d + q) : 0.f;
        }
    } else if (base < N0 + N1) {
        int r = base - N0;
        int n = r / DP, d = r % DP;
        int mat = n / 160, h = n % 160;
        dst = g_Wabm + r;
        const float* src = (mat == 0) ? w1p : (mat == 1) ? (w1p + D_ * H_) : w1m;
        #pragma unroll
        for (int q = 0; q < 8; ++q)
            v[q] = (h < H_ && d + q < D_) ? __ldg(src + (d + q) * H_ + h) : 0.f;
    } else {
        int r = base - N0 - N1;
        int h = r / DP, d = r % DP;
        dst = g_Wt + r;
        const float* src = w1p + 2 * D_ * H_;
        #pragma unroll
        for (int q = 0; q < 8; ++q)
            v[q] = (h < H_ && d + q < D_) ? __ldg(src + (d + q) * H_ + h) : 0.f;
    }
    uint4 o;
    CVT_BF2(o.x, v[0], v[1]);
    CVT_BF2(o.y, v[2], v[3]);
    CVT_BF2(o.z, v[4], v[5]);
    CVT_BF2(o.w, v[6], v[7]);
    *(uint4*)dst = o;
}

// ============================ bf16 MMA GEMM for P/Q + fused ment (M=32 tiles) ============================
__global__ __launch_bounds__(256) void gemm_mma_kernel(
    const float* __restrict__ b1m, const float* __restrict__ w2m, const float* __restrict__ b2m)
{
    __shared__ __align__(16) unsigned char Asm[32 * 80];
    __shared__ __align__(16) unsigned char Bsm[160 * 80];
    __shared__ float mpart[4][32];

    const int tid = threadIdx.x;
    const int wid = tid >> 5;
    const int lane = tid & 31;
    const int row0 = blockIdx.x * 32;
    const int mat = blockIdx.y;
    const char* Bsrc = (const char*)(g_Wabm + mat * 160 * DP);

    const int mhalf = wid & 1;
    const int ngrp4 = wid >> 1;

    const uint32_t Ab = smem_u32(Asm);
    const uint32_t Bb = smem_u32(Bsm);
    const uint32_t a_off = Ab + (uint32_t)((mhalf * 16 + (lane & 15)) * 80 + ((lane >> 4) & 1) * 16);
    const uint32_t b_off = Bb + (uint32_t)((ngrp4 * 40 + (lane & 7)) * 80 + ((lane >> 3) & 1) * 16);

    float acc[5][4];
    #pragma unroll
    for (int nt = 0; nt < 5; ++nt)
        #pragma unroll
        for (int q = 0; q < 4; ++q) acc[nt][q] = 0.f;

    for (int c = 0; c < NCH; ++c) {
        if (tid < 128) {
            int r = tid >> 2, grp = tid & 3;
            uint4 v = __ldg((const uint4*)((const char*)g_Xb + (row0 + r) * XB_ROWB + c * 64 + grp * 16));
            *(uint4*)(Asm + r * 80 + grp * 16) = v;
        }
        for (int idx = tid; idx < 640; idx += 256) {
            int h = idx >> 2, grp = idx & 3;
            uint4 v = __ldg((const uint4*)(Bsrc + h * XB_ROWB + c * 64 + grp * 16));
            *(uint4*)(Bsm + h * 80 + grp * 16) = v;
        }
        __syncthreads();
        #pragma unroll
        for (int k16 = 0; k16 < 2; ++k16) {
            uint32_t a0, a1, a2, a3;
            LDSM_X4(a0, a1, a2, a3, a_off + k16 * 32);
            #pragma unroll
            for (int nt = 0; nt < 5; ++nt) {
                uint32_t b0, b1;
                LDSM_X2(b0, b1, b_off + nt * 640 + k16 * 32);
                MMA16816(acc[nt], a0, a1, a2, a3, b0, b1);
            }
        }
        __syncthreads();
    }

    const int g = lane >> 2, t = lane & 3;
    if (mat < 2) {
        float* dst = (mat == 0) ? g_P : g_Q;
        #pragma unroll
        for (int nt = 0; nt < 5; ++nt) {
            int h = ngrp4 * 40 + nt * 8 + t * 2;
            if (h < H_) {
                int ra = row0 + mhalf * 16 + g;
                dst[ra * H_ + h]           = acc[nt][0];
                dst[ra * H_ + h + 1]       = acc[nt][1];
                dst[(ra + 8) * H_ + h]     = acc[nt][2];
                dst[(ra + 8) * H_ + h + 1] = acc[nt][3];
            }
        }
    } else {
        float s0 = 0.f, s1 = 0.f;
        #pragma unroll
        for (int nt = 0; nt < 5; ++nt) {
            int h = ngrp4 * 40 + nt * 8 + t * 2;
            if (h < H_) {
                float ba = __ldg(b1m + h), bb = __ldg(b1m + h + 1);
                float wa = __ldg(w2m + h), wb = __ldg(w2m + h + 1);
                s0 += fmaxf(acc[nt][0] + ba, 0.f) * wa + fmaxf(acc[nt][1] + bb, 0.f) * wb;
                s1 += fmaxf(acc[nt][2] + ba, 0.f) * wa + fmaxf(acc[nt][3] + bb, 0.f) * wb;
            }
        }
        s0 += __shfl_xor_sync(0xffffffffu, s0, 1);
        s0 += __shfl_xor_sync(0xffffffffu, s0, 2);
        s1 += __shfl_xor_sync(0xffffffffu, s1, 1);
        s1 += __shfl_xor_sync(0xffffffffu, s1, 2);
        int rl = mhalf * 16 + g;
        if (t == 0) {
            mpart[ngrp4][rl] = s0;
            mpart[ngrp4][rl + 8] = s1;
        }
        __syncthreads();
        if (tid < 32)
            g_ment[row0 + tid] = mpart[0][tid] + mpart[1][tid] + mpart[2][tid] + mpart[3][tid]
                                 + __ldg(b2m);
    }
}

// ============================ score: N-split, 2 CTAs/SM, 8-stage ring ============================
// grid (410, 2), 256 threads. blockIdx.y = nh (h-half). Warp wid owns rows wid*32..+31, all 80 local cols.
__global__ __launch_bounds__(256, 2) void score_mma_kernel(
    const float* __restrict__ b1p,
    const float* __restrict__ w2p)
{
    extern __shared__ __align__(16) unsigned char sm[];
    const int tid = threadIdx.x;
    const int wid = tid >> 5;
    const int lane = tid & 31;
    const int i0 = blockIdx.x * GPC;
    const int nh = blockIdx.y;

    float* Ps = (float*)(sm + SPS);      // [5][80]
    float* w2ps = (float*)(sm + SW2);    // [80]
    const uint32_t Sb = smem_u32(sm);

    // cp.async task mapping (per thread, per chunk):
    //  slot A (tid<224): XW row tid>>2, grp tid&3
    //  slot B0 (all 256): B local row tid>>2 (0..63), grp tid&3
    //  slot B1 (tid<64):  B local row 64 + (tid>>2), grp tid&3
    uint32_t dstA = 0; const char* srcA = nullptr;
    if (tid < 224) {
        int rr = tid >> 2, grp = tid & 3;
        int gr = i0 - K_ + rr;
        if (gr < 0) gr = 0; if (gr > M_ - 1) gr = M_ - 1;
        dstA = Sb + SXW + (uint32_t)(rr * XWST + grp * 16);
        srcA = (const char*)g_Xb + gr * XB_ROWB + grp * 16;
    }
    uint32_t dstB0, dstB1 = 0; const char* srcB0; const char* srcB1 = nullptr;
    {
        int hl = tid >> 2, grp = tid & 3;
        dstB0 = Sb + SB + (uint32_t)(hl * 80 + grp * 16);
        srcB0 = (const char*)g_Wt + (nh * 80 + hl) * XB_ROWB + grp * 16;
        if (tid < 64) {
            dstB1 = Sb + SB + (uint32_t)((64 + hl) * 80 + grp * 16);
            srcB1 = (const char*)g_Wt + (nh * 80 + 64 + hl) * XB_ROWB + grp * 16;
        }
    }

    // prologue: chunks 0,1 (group 1), 2,3 (group 2)
    #pragma unroll
    for (int cn = 0; cn < 2; ++cn) {
        uint32_t so = (uint32_t)cn;
        if (tid < 224) cp16(dstA + so * XWSZ, srcA + cn * 64);
        cp16(dstB0 + so * BSZ, srcB0 + cn * 64);
        if (tid < 64) cp16(dstB1 + so * BSZ, srcB1 + cn * 64);
    }
    CP_COMMIT();
    #pragma unroll
    for (int cn = 2; cn < 4; ++cn) {
        uint32_t so = (uint32_t)cn;
        if (tid < 224) cp16(dstA + so * XWSZ, srcA + cn * 64);
        cp16(dstB0 + so * BSZ, srcB0 + cn * 64);
        if (tid < 64) cp16(dstB1 + so * BSZ, srcB1 + cn * 64);
    }
    CP_COMMIT();

    // stage Ps / w2p (own 80-col half)
    for (int idx = tid; idx < GPC * 80; idx += 256) {
        int m = idx / 80, hl = idx % 80;
        int i = i0 + m; if (i > M_ - 1) i = M_ - 1;
        int h = nh * 80 + hl;
        Ps[idx] = (h < H_) ? (g_P[i * H_ + h] + b1p[h]) : 0.f;
    }
    for (int idx = tid; idx < 80; idx += 256) {
        int h = nh * 80 + idx;
        w2ps[idx] = (h < H_) ? w2p[h] : 0.f;
    }

    // per-lane ldmatrix A addresses (within-stage offsets)
    uint32_t axi[2], axj[2];
    {
        const int colh = ((lane >> 4) & 1) * 16;
        #pragma unroll
        for (int t = 0; t < 2; ++t) {
            int ra = wid * 32 + t * 16 + (lane & 15);
            int m = ra / 50;
            int k = ra - m * 50;
            if (m > 4) { m = 4; k = 49; }   // pad rows: in-bounds garbage, masked later
            axi[t] = (uint32_t)((50 + m) * XWST + colh);
            axj[t] = (uint32_t)((m + k) * XWST + colh);
        }
    }
    const uint32_t b_off = (uint32_t)((((lane >> 4) & 1) * 8 + (lane & 7)) * 80
                                      + ((lane >> 3) & 1) * 16);

    float acc[2][10][4];
    #pragma unroll
    for (int t = 0; t < 2; ++t)
        #pragma unroll
        for (int nt = 0; nt < 10; ++nt)
            #pragma unroll
            for (int q = 0; q < 4; ++q) acc[t][nt][q] = 0.f;

    // main loop: 15 periods of 2 chunks
    for (int p = 0; p < 15; ++p) {
        CP_WAIT1();
        __syncthreads();
        // issue fills for chunks 2p+4, 2p+5
        #pragma unroll
        for (int q = 0; q < 2; ++q) {
            int cn = 2 * p + 4 + q;
            if (cn < NCH) {
                uint32_t stg = (uint32_t)(cn % NSTG);
                if (tid < 224) cp16(dstA + stg * XWSZ, srcA + cn * 64);
                cp16(dstB0 + stg * BSZ, srcB0 + cn * 64);
                if (tid < 64) cp16(dstB1 + stg * BSZ, srcB1 + cn * 64);
            }
        }
        CP_COMMIT();
        // MMA on chunks 2p, 2p+1
        #pragma unroll
        for (int q = 0; q < 2; ++q) {
            int c = 2 * p + q;
            if (c < NCH) {
                uint32_t stg = (uint32_t)(c % NSTG);
                const uint32_t xwb = Sb + SXW + stg * XWSZ;
                const uint32_t bbb = Sb + SB + stg * BSZ + b_off;
                #pragma unroll
                for (int k16 = 0; k16 < 2; ++k16) {
                    uint32_t a0[4], a1[4];
                    {
                        uint32_t xi0, xi1, xi2, xi3, xj0, xj1, xj2, xj3;
                        LDSM_X4(xi0, xi1, xi2, xi3, xwb + axi[0] + k16 * 32);
                        LDSM_X4(xj0, xj1, xj2, xj3, xwb + axj[0] + k16 * 32);
                        a0[0] = bf2mul(xi0, xj0); a0[1] = bf2mul(xi1, xj1);
                        a0[2] = bf2mul(xi2, xj2); a0[3] = bf2mul(xi3, xj3);
                        LDSM_X4(xi0, xi1, xi2, xi3, xwb + axi[1] + k16 * 32);
                        LDSM_X4(xj0, xj1, xj2, xj3, xwb + axj[1] + k16 * 32);
                        a1[0] = bf2mul(xi0, xj0); a1[1] = bf2mul(xi1, xj1);
                        a1[2] = bf2mul(xi2, xj2); a1[3] = bf2mul(xi3, xj3);
                    }
                    // B-fragment pipeline: prefetch pp+1 before MMAs of pp
                    uint32_t bc0, bc1, bc2, bc3;
                    LDSM_X4(bc0, bc1, bc2, bc3, bbb + k16 * 32);
                    #pragma unroll
                    for (int pp = 0; pp < 5; ++pp) {
                        uint32_t bn0, bn1, bn2, bn3;
                        if (pp < 4) LDSM_X4(bn0, bn1, bn2, bn3, bbb + (pp + 1) * 1280 + k16 * 32);
                        MMA16816(acc[0][2 * pp],     a0[0], a0[1], a0[2], a0[3], bc0, bc1);
                        MMA16816(acc[0][2 * pp + 1], a0[0], a0[1], a0[2], a0[3], bc2, bc3);
                        MMA16816(acc[1][2 * pp],     a1[0], a1[1], a1[2], a1[3], bc0, bc1);
                        MMA16816(acc[1][2 * pp + 1], a1[0], a1[1], a1[2], a1[3], bc2, bc3);
                        if (pp < 4) { bc0 = bn0; bc1 = bn1; bc2 = bn2; bc3 = bn3; }
                    }
                }
            }
        }
    }

    // ---- epilogue: 80-col dot partials -> g_sp[nh] ----
    const int g = lane >> 2, t4 = lane & 3;
    #pragma unroll
    for (int t = 0; t < 2; ++t) {
        #pragma unroll
        for (int half = 0; half < 2; ++half) {
            const int r = wid * 32 + t * 16 + half * 8 + g;
            float p = 0.f;
            if (r < 250) {
                const int m = r / 50, k = r - m * 50;
                const int i = i0 + m;
                const int j = i0 + m + k - K_;
                if (i < M_ && j >= 0) {
                    const float* qrow = g_Q + j * H_;
                    const float* prow = Ps + m * 80;
                    #pragma unroll
                    for (int nt = 0; nt < 10; ++nt) {
                        int hl = nt * 8 + t4 * 2;
                        int h = nh * 80 + hl;
                        if (h < H_) {
                            float a = acc[t][nt][half * 2]     + prow[hl]     + __ldg(qrow + h);
                            float b = acc[t][nt][half * 2 + 1] + prow[hl + 1] + __ldg(qrow + h + 1);
                            p += fmaxf(a, 0.f) * w2ps[hl] + fmaxf(b, 0.f) * w2ps[hl + 1];
                        }
                    }
                }
                p += __shfl_xor_sync(0xffffffffu, p, 1);
                p += __shfl_xor_sync(0xffffffffu, p, 2);
                if (t4 == 0 && i < M_) g_sp[nh][i * K_ + k] = p;
            } else {
                // keep shfl participation uniform
                p += __shfl_xor_sync(0xffffffffu, p, 1);
                p += __shfl_xor_sync(0xffffffffu, p, 2);
            }
        }
    }
}

// ============================ combine ============================
__global__ __launch_bounds__(256) void combine_kernel(
    const float* __restrict__ b2p, float* __restrict__ out)
{
    int idx = blockIdx.x * 256 + threadIdx.x;
    if (idx >= M_ * (K_ + 1)) return;
    int i = idx / (K_ + 1), k = idx % (K_ + 1);
    float v;
    if (k == K_) {
        v = 0.f;
    } else {
        int j = i + k - K_;
        v = (j >= 0)
            ? (g_ment[i] + g_ment[j] + __ldg(b2p) + g_sp[0][i * K_ + k] + g_sp[1][i * K_ + k])
            : NEG_;
    }
    out[idx] = v;
}

// ============================ launcher ============================
extern "C" void kernel_launch(void* const* d_in, const int* in_sizes, int n_in,
                              void* d_out, int out_size)
{
    const float* X   = (const float*)d_in[0];
    const float* w1m = (const float*)d_in[1];
    const float* b1m = (const float*)d_in[2];
    const float* w2m = (const float*)d_in[3];
    const float* b2m = (const float*)d_in[4];
    const float* w1p = (const float*)d_in[5];
    const float* b1p = (const float*)d_in[6];
    const float* w2p = (const float*)d_in[7];
    const float* b2p = (const float*)d_in[8];
    float* out = (float*)d_out;

    cudaFuncSetAttribute(score_mma_kernel,
                         cudaFuncAttributeMaxDynamicSharedMemorySize, SSZ);

    prep_kernel<<<(TOT8 + 255) / 256, 256>>>(X, w1p, w1m);
    gemm_mma_kernel<<<dim3(64, 3), 256>>>(b1m, w2m, b2m);
    score_mma_kernel<<<dim3(SGRID, 2), 256, SSZ>>>(b1p, w2p);
    combine_kernel<<<(M_ * (K_ + 1) + 255) / 256, 256>>>(b2p, out);
}